// round 1
// baseline (speedup 1.0000x reference)
#include <cuda_runtime.h>
#include <math.h>

#define BB 8
#define QQL 1024
#define KKL 1024
#define DDIM 1024
#define NH 16
#define HDIM 64
#define FFD 4096
#define MROWS (BB*QQL)   /* 8192 */

// ---------------- scratch (device globals: allocation-free rule) ----------------
__device__ float g_qn[(size_t)MROWS * DDIM];
__device__ float g_kvn[(size_t)BB * KKL * DDIM];
__device__ float g_q[(size_t)MROWS * DDIM];
__device__ float g_k[(size_t)BB * KKL * DDIM];
__device__ float g_v[(size_t)BB * KKL * DDIM];
__device__ float g_scores[(size_t)BB * NH * QQL * KKL];   // 512 MB
__device__ float g_attnout[(size_t)MROWS * DDIM];
__device__ float g_x[(size_t)MROWS * DDIM];
__device__ float g_lnf[(size_t)MROWS * DDIM];
__device__ float g_h[(size_t)MROWS * FFD];
__device__ int   g_mask_flag;   // 0=int32, 1=uint8, 2=float32

// ---------------- mask dtype sniffing ----------------
__global__ void detect_mask_kernel(const unsigned char* __restrict__ m) {
    __shared__ int c1, c2, c3;
    if (threadIdx.x == 0) { c1 = 0; c2 = 0; c3 = 0; }
    __syncthreads();
    // scan first 8192 bytes: safe for uint8 (exactly 8192B), int32/float32 (32KB)
    for (int i = threadIdx.x; i < BB * KKL; i += blockDim.x) {
        unsigned char v = m[i];
        if (v) {
            int p = i & 3;
            if (p == 1) atomicAdd(&c1, 1);
            else if (p == 2) atomicAdd(&c2, 1);
            else if (p == 3) atomicAdd(&c3, 1);
        }
    }
    __syncthreads();
    if (threadIdx.x == 0) {
        int f;
        if (c1 == 0 && c2 == 0 && c3 == 0) f = 0;  // int32 0/1: only byte 0 of each word set
        else if (c1 == 0) f = 2;                   // float32 1.0f = 00 00 80 3f
        else f = 1;                                // uint8 bool
        g_mask_flag = f;
    }
}

__device__ __forceinline__ bool mask_valid(const void* m, int idx, int flag) {
    if (flag == 1) return ((const unsigned char*)m)[idx] != 0;
    if (flag == 2) return ((const float*)m)[idx] != 0.0f;
    return ((const int*)m)[idx] != 0;
}

// ---------------- layernorm ----------------
__global__ void __launch_bounds__(256) layernorm_kernel(
    const float* __restrict__ x, const float* __restrict__ w,
    const float* __restrict__ b, float* __restrict__ out)
{
    int row = blockIdx.x;
    const float* xr = x + (size_t)row * DDIM;
    float sum = 0.f, sumsq = 0.f;
    for (int i = threadIdx.x; i < DDIM; i += blockDim.x) {
        float v = xr[i]; sum += v; sumsq += v * v;
    }
    __shared__ float s1[32], s2[32];
    for (int o = 16; o; o >>= 1) {
        sum   += __shfl_down_sync(0xffffffffu, sum, o);
        sumsq += __shfl_down_sync(0xffffffffu, sumsq, o);
    }
    int lane = threadIdx.x & 31, wid = threadIdx.x >> 5;
    if (lane == 0) { s1[wid] = sum; s2[wid] = sumsq; }
    __syncthreads();
    if (wid == 0) {
        sum   = lane < 8 ? s1[lane] : 0.f;
        sumsq = lane < 8 ? s2[lane] : 0.f;
        for (int o = 4; o; o >>= 1) {
            sum   += __shfl_down_sync(0xffffffffu, sum, o);
            sumsq += __shfl_down_sync(0xffffffffu, sumsq, o);
        }
        if (lane == 0) { s1[0] = sum; s2[0] = sumsq; }
    }
    __syncthreads();
    float mu  = s1[0] * (1.0f / DDIM);
    float var = s2[0] * (1.0f / DDIM) - mu * mu;
    float inv = rsqrtf(var + 1e-5f);
    float* orow = out + (size_t)row * DDIM;
    for (int i = threadIdx.x; i < DDIM; i += blockDim.x)
        orow[i] = (xr[i] - mu) * inv * w[i] + b[i];
}

// ---------------- generic TN SGEMM: C[M,N] = A[M,Kd] * W[N,Kd]^T (+bias, +resid, gelu) ----------------
// grid: (N/64, M/64), 256 threads. Kd % 16 == 0, M,N % 64 == 0.
__device__ __forceinline__ float gelu_exact(float v) {
    return 0.5f * v * (1.0f + erff(v * 0.70710678118654752f));
}

__global__ void __launch_bounds__(256) gemm_tn_kernel(
    const float* __restrict__ A, const float* __restrict__ W,
    const float* __restrict__ bias, const float* __restrict__ resid,
    float* __restrict__ C, int Kd, int N, int act)
{
    __shared__ float As[16][68];
    __shared__ float Bs[16][68];
    int bm = blockIdx.y * 64, bn = blockIdx.x * 64;
    int tid = threadIdx.x;
    int tx = tid & 15, ty = tid >> 4;
    int lr = tid >> 2;          // 0..63
    int lk = (tid & 3) * 4;     // 0,4,8,12
    const float* Ap = A + (size_t)(bm + lr) * Kd + lk;
    const float* Wp = W + (size_t)(bn + lr) * Kd + lk;
    float acc[4][4] = {};
    for (int k0 = 0; k0 < Kd; k0 += 16) {
        float4 a = *(const float4*)(Ap + k0);
        float4 w = *(const float4*)(Wp + k0);
        __syncthreads();
        As[lk + 0][lr] = a.x; As[lk + 1][lr] = a.y; As[lk + 2][lr] = a.z; As[lk + 3][lr] = a.w;
        Bs[lk + 0][lr] = w.x; Bs[lk + 1][lr] = w.y; Bs[lk + 2][lr] = w.z; Bs[lk + 3][lr] = w.w;
        __syncthreads();
#pragma unroll
        for (int kk = 0; kk < 16; kk++) {
            float4 av = *(const float4*)&As[kk][ty * 4];
            float4 bv = *(const float4*)&Bs[kk][tx * 4];
            acc[0][0] += av.x * bv.x; acc[0][1] += av.x * bv.y; acc[0][2] += av.x * bv.z; acc[0][3] += av.x * bv.w;
            acc[1][0] += av.y * bv.x; acc[1][1] += av.y * bv.y; acc[1][2] += av.y * bv.z; acc[1][3] += av.y * bv.w;
            acc[2][0] += av.z * bv.x; acc[2][1] += av.z * bv.y; acc[2][2] += av.z * bv.z; acc[2][3] += av.z * bv.w;
            acc[3][0] += av.w * bv.x; acc[3][1] += av.w * bv.y; acc[3][2] += av.w * bv.z; acc[3][3] += av.w * bv.w;
        }
    }
#pragma unroll
    for (int i = 0; i < 4; i++) {
        int m = bm + ty * 4 + i;
#pragma unroll
        for (int j = 0; j < 4; j++) {
            int n = bn + tx * 4 + j;
            float v = acc[i][j];
            if (bias)  v += bias[n];
            if (resid) v += resid[(size_t)m * N + n];
            if (act)   v = gelu_exact(v);
            C[(size_t)m * N + n] = v;
        }
    }
}

// ---------------- batched scores: S[b,h,q,k] = scale * <q_bh[q,:], k_bh[k,:]> ----------------
// grid: (K/64, Q/64, B*H)
__global__ void __launch_bounds__(256) scores_kernel(
    const float* __restrict__ qb, const float* __restrict__ kb, float* __restrict__ S)
{
    int z = blockIdx.z;
    int b = z / NH, h = z % NH;
    const float* A = qb + (size_t)b * QQL * DDIM + h * HDIM;
    const float* W = kb + (size_t)b * KKL * DDIM + h * HDIM;
    float* C = S + (size_t)z * QQL * KKL;

    __shared__ float As[16][68];
    __shared__ float Bs[16][68];
    int bm = blockIdx.y * 64, bn = blockIdx.x * 64;
    int tid = threadIdx.x;
    int tx = tid & 15, ty = tid >> 4;
    int lr = tid >> 2;
    int lk = (tid & 3) * 4;
    const float* Ap = A + (size_t)(bm + lr) * DDIM + lk;
    const float* Wp = W + (size_t)(bn + lr) * DDIM + lk;
    float acc[4][4] = {};
#pragma unroll
    for (int k0 = 0; k0 < HDIM; k0 += 16) {
        float4 a = *(const float4*)(Ap + k0);
        float4 w = *(const float4*)(Wp + k0);
        __syncthreads();
        As[lk + 0][lr] = a.x; As[lk + 1][lr] = a.y; As[lk + 2][lr] = a.z; As[lk + 3][lr] = a.w;
        Bs[lk + 0][lr] = w.x; Bs[lk + 1][lr] = w.y; Bs[lk + 2][lr] = w.z; Bs[lk + 3][lr] = w.w;
        __syncthreads();
#pragma unroll
        for (int kk = 0; kk < 16; kk++) {
            float4 av = *(const float4*)&As[kk][ty * 4];
            float4 bv = *(const float4*)&Bs[kk][tx * 4];
            acc[0][0] += av.x * bv.x; acc[0][1] += av.x * bv.y; acc[0][2] += av.x * bv.z; acc[0][3] += av.x * bv.w;
            acc[1][0] += av.y * bv.x; acc[1][1] += av.y * bv.y; acc[1][2] += av.y * bv.z; acc[1][3] += av.y * bv.w;
            acc[2][0] += av.z * bv.x; acc[2][1] += av.z * bv.y; acc[2][2] += av.z * bv.z; acc[2][3] += av.z * bv.w;
            acc[3][0] += av.w * bv.x; acc[3][1] += av.w * bv.y; acc[3][2] += av.w * bv.z; acc[3][3] += av.w * bv.w;
        }
    }
    const float scale = 0.125f;  // 1/sqrt(64)
#pragma unroll
    for (int i = 0; i < 4; i++) {
        int m = bm + ty * 4 + i;
#pragma unroll
        for (int j = 0; j < 4; j++) {
            int n = bn + tx * 4 + j;
            C[(size_t)m * KKL + n] = acc[i][j] * scale;
        }
    }
}

// ---------------- masked softmax over K (in place) ----------------
// grid: B*H*Q blocks, 256 threads
__global__ void __launch_bounds__(256) softmax_kernel(float* __restrict__ S, const void* __restrict__ mask)
{
    size_t row = blockIdx.x;
    int b = (int)(row / ((size_t)NH * QQL));
    float* r = S + row * (size_t)KKL;
    int flag = g_mask_flag;
    int t = threadIdx.x;

    float vals[4];
    float mx = -1e30f;
#pragma unroll
    for (int i = 0; i < 4; i++) {
        int k = t + i * 256;
        bool valid = mask_valid(mask, b * KKL + k, flag);
        float v = valid ? r[k] : -__int_as_float(0x7f800000);  // -inf
        vals[i] = v;
        mx = fmaxf(mx, v);
    }
    __shared__ float red[256];
    red[t] = mx; __syncthreads();
    for (int s = 128; s; s >>= 1) { if (t < s) red[t] = fmaxf(red[t], red[t + s]); __syncthreads(); }
    mx = red[0]; __syncthreads();

    float sum = 0.f;
#pragma unroll
    for (int i = 0; i < 4; i++) {
        float e = expf(vals[i] - mx);   // exp(-inf - mx) = 0
        vals[i] = e;
        sum += e;
    }
    red[t] = sum; __syncthreads();
    for (int s = 128; s; s >>= 1) { if (t < s) red[t] += red[t + s]; __syncthreads(); }
    float inv = 1.0f / red[0];
#pragma unroll
    for (int i = 0; i < 4; i++)
        r[t + i * 256] = vals[i] * inv;
}

// ---------------- mean over heads: out[b,q,k] = (1/H) sum_h attn[b,h,q,k] ----------------
__global__ void __launch_bounds__(256) mean_heads_kernel(const float* __restrict__ attn, float* __restrict__ out)
{
    size_t idx = (size_t)blockIdx.x * blockDim.x + threadIdx.x;
    if (idx >= (size_t)BB * QQL * KKL) return;
    int k = (int)(idx % KKL);
    size_t t = idx / KKL;
    int q = (int)(t % QQL);
    int b = (int)(t / QQL);
    float s = 0.f;
#pragma unroll
    for (int h = 0; h < NH; h++)
        s += attn[(((size_t)b * NH + h) * QQL + q) * KKL + k];
    out[idx] = s * (1.0f / NH);
}

// ---------------- batched NN: out[b,q, h*HD+n] = sum_k attn[b,h,q,k] * v[b,k,h*HD+n] ----------------
// grid: (1, Q/64, B*H)
__global__ void __launch_bounds__(256) av_kernel(
    const float* __restrict__ attn, const float* __restrict__ vb, float* __restrict__ out)
{
    int z = blockIdx.z;
    int b = z / NH, h = z % NH;
    const float* A = attn + (size_t)z * QQL * KKL;              // [Q, K], lda=K
    const float* Bm = vb + (size_t)b * KKL * DDIM + h * HDIM;   // [K, 64], ldb=D
    float* C = out + (size_t)b * QQL * DDIM + h * HDIM;         // [Q, 64], ldc=D

    __shared__ float As[16][68];
    __shared__ float Bs[16][68];
    int bm = blockIdx.y * 64;
    int tid = threadIdx.x;
    int tx = tid & 15, ty = tid >> 4;
    // A load (transpose): row lr, k chunk lk
    int lr = tid >> 2;
    int lk = (tid & 3) * 4;
    // B load (direct): row brow (k), col bcol4
    int brow = tid >> 4;          // 0..15
    int bcol = (tid & 15) * 4;    // 0..60
    const float* Ap = A + (size_t)(bm + lr) * KKL + lk;
    float acc[4][4] = {};
    for (int k0 = 0; k0 < KKL; k0 += 16) {
        float4 a = *(const float4*)(Ap + k0);
        float4 w = *(const float4*)(Bm + (size_t)(k0 + brow) * DDIM + bcol);
        __syncthreads();
        As[lk + 0][lr] = a.x; As[lk + 1][lr] = a.y; As[lk + 2][lr] = a.z; As[lk + 3][lr] = a.w;
        *(float4*)&Bs[brow][bcol] = w;
        __syncthreads();
#pragma unroll
        for (int kk = 0; kk < 16; kk++) {
            float4 av = *(const float4*)&As[kk][ty * 4];
            float4 bv = *(const float4*)&Bs[kk][tx * 4];
            acc[0][0] += av.x * bv.x; acc[0][1] += av.x * bv.y; acc[0][2] += av.x * bv.z; acc[0][3] += av.x * bv.w;
            acc[1][0] += av.y * bv.x; acc[1][1] += av.y * bv.y; acc[1][2] += av.y * bv.z; acc[1][3] += av.y * bv.w;
            acc[2][0] += av.z * bv.x; acc[2][1] += av.z * bv.y; acc[2][2] += av.z * bv.z; acc[2][3] += av.z * bv.w;
            acc[3][0] += av.w * bv.x; acc[3][1] += av.w * bv.y; acc[3][2] += av.w * bv.z; acc[3][3] += av.w * bv.w;
        }
    }
#pragma unroll
    for (int i = 0; i < 4; i++) {
        int m = bm + ty * 4 + i;
#pragma unroll
        for (int j = 0; j < 4; j++) {
            int n = tx * 4 + j;
            C[(size_t)m * DDIM + n] = acc[i][j];
        }
    }
}

// ---------------- launch ----------------
extern "C" void kernel_launch(void* const* d_in, const int* in_sizes, int n_in,
                              void* d_out, int out_size)
{
    const float* query      = (const float*)d_in[0];
    const float* key_value  = (const float*)d_in[1];
    const void*  kpm        = d_in[2];
    const float* ln_q_w     = (const float*)d_in[3];
    const float* ln_q_b     = (const float*)d_in[4];
    const float* ln_kv_w    = (const float*)d_in[5];
    const float* ln_kv_b    = (const float*)d_in[6];
    const float* ln_f_w     = (const float*)d_in[7];
    const float* ln_f_b     = (const float*)d_in[8];
    const float* in_proj_w  = (const float*)d_in[9];
    const float* in_proj_b  = (const float*)d_in[10];
    const float* out_proj_w = (const float*)d_in[11];
    const float* out_proj_b = (const float*)d_in[12];
    const float* ffn_w1     = (const float*)d_in[13];
    const float* ffn_b1     = (const float*)d_in[14];
    const float* ffn_w2     = (const float*)d_in[15];
    const float* ffn_b2     = (const float*)d_in[16];

    float* out_x    = (float*)d_out;                       // (B,Q,D)
    float* out_attn = out_x + (size_t)BB * QQL * DDIM;     // (B,Q,K)

    float *qn, *kvn, *qp, *kp, *vp, *sc, *ao, *xb, *lnf, *hb;
    cudaGetSymbolAddress((void**)&qn,  g_qn);
    cudaGetSymbolAddress((void**)&kvn, g_kvn);
    cudaGetSymbolAddress((void**)&qp,  g_q);
    cudaGetSymbolAddress((void**)&kp,  g_k);
    cudaGetSymbolAddress((void**)&vp,  g_v);
    cudaGetSymbolAddress((void**)&sc,  g_scores);
    cudaGetSymbolAddress((void**)&ao,  g_attnout);
    cudaGetSymbolAddress((void**)&xb,  g_x);
    cudaGetSymbolAddress((void**)&lnf, g_lnf);
    cudaGetSymbolAddress((void**)&hb,  g_h);

    detect_mask_kernel<<<1, 256>>>((const unsigned char*)kpm);

    layernorm_kernel<<<MROWS, 256>>>(query, ln_q_w, ln_q_b, qn);
    layernorm_kernel<<<BB * KKL, 256>>>(key_value, ln_kv_w, ln_kv_b, kvn);

    dim3 gproj(DDIM / 64, MROWS / 64);
    const float* Wq = in_proj_w;
    const float* Wk = in_proj_w + (size_t)DDIM * DDIM;
    const float* Wv = in_proj_w + 2 * (size_t)DDIM * DDIM;
    gemm_tn_kernel<<<gproj, 256>>>(qn,  Wq, in_proj_b,            nullptr, qp, DDIM, DDIM, 0);
    gemm_tn_kernel<<<gproj, 256>>>(kvn, Wk, in_proj_b + DDIM,     nullptr, kp, DDIM, DDIM, 0);
    gemm_tn_kernel<<<gproj, 256>>>(kvn, Wv, in_proj_b + 2 * DDIM, nullptr, vp, DDIM, DDIM, 0);

    dim3 gsc(KKL / 64, QQL / 64, BB * NH);
    scores_kernel<<<gsc, 256>>>(qp, kp, sc);

    softmax_kernel<<<BB * NH * QQL, 256>>>(sc, kpm);

    mean_heads_kernel<<<(BB * QQL * KKL) / 256, 256>>>(sc, out_attn);

    dim3 gav(1, QQL / 64, BB * NH);
    av_kernel<<<gav, 256>>>(sc, vp, ao);

    // x = query + attn_out @ Wo^T + bo
    gemm_tn_kernel<<<gproj, 256>>>(ao, out_proj_w, out_proj_b, query, xb, DDIM, DDIM, 0);

    layernorm_kernel<<<MROWS, 256>>>(xb, ln_f_w, ln_f_b, lnf);

    dim3 gff1(FFD / 64, MROWS / 64);
    gemm_tn_kernel<<<gff1, 256>>>(lnf, ffn_w1, ffn_b1, nullptr, hb, DDIM, FFD, 1);

    // out_x = x + h @ W2^T + b2
    gemm_tn_kernel<<<gproj, 256>>>(hb, ffn_w2, ffn_b2, xb, out_x, FFD, DDIM, 0);
}

// round 3
// speedup vs baseline: 1.9493x; 1.9493x over previous
#include <cuda_runtime.h>
#include <cuda_bf16.h>
#include <math.h>
#include <stdint.h>

#define BB 8
#define QQL 1024
#define KKL 1024
#define DDIM 1024
#define NH 16
#define HDIM 64
#define FFD 4096
#define MROWS (BB*QQL)   /* 8192 */

// ---------------- scratch (device globals: allocation-free rule) ----------------
// bf16 split planes
__device__ __nv_bfloat16 g_qn_h[(size_t)MROWS * DDIM],  g_qn_l[(size_t)MROWS * DDIM];
__device__ __nv_bfloat16 g_kvn_h[(size_t)MROWS * DDIM], g_kvn_l[(size_t)MROWS * DDIM];
__device__ __nv_bfloat16 g_lnf_h[(size_t)MROWS * DDIM], g_lnf_l[(size_t)MROWS * DDIM];
__device__ __nv_bfloat16 g_ao_h[(size_t)MROWS * DDIM],  g_ao_l[(size_t)MROWS * DDIM];
__device__ __nv_bfloat16 g_hh[(size_t)MROWS * FFD],     g_hl[(size_t)MROWS * FFD];
__device__ __nv_bfloat16 g_w_h[(size_t)12 * 1024 * 1024], g_w_l[(size_t)12 * 1024 * 1024];
// fp32 buffers
__device__ float g_q[(size_t)MROWS * DDIM];
__device__ float g_k[(size_t)MROWS * DDIM];
__device__ float g_v[(size_t)MROWS * DDIM];
__device__ float g_scores[(size_t)BB * NH * QQL * KKL];   // 512 MB
__device__ float g_attnout[(size_t)MROWS * DDIM];
__device__ float g_x[(size_t)MROWS * DDIM];
__device__ int   g_mask_flag;

// ---------------- mask dtype sniffing ----------------
__global__ void detect_mask_kernel(const unsigned char* __restrict__ m) {
    __shared__ int c1, c2, c3;
    if (threadIdx.x == 0) { c1 = 0; c2 = 0; c3 = 0; }
    __syncthreads();
    for (int i = threadIdx.x; i < BB * KKL; i += blockDim.x) {
        unsigned char v = m[i];
        if (v) {
            int p = i & 3;
            if (p == 1) atomicAdd(&c1, 1);
            else if (p == 2) atomicAdd(&c2, 1);
            else if (p == 3) atomicAdd(&c3, 1);
        }
    }
    __syncthreads();
    if (threadIdx.x == 0) {
        int f;
        if (c1 == 0 && c2 == 0 && c3 == 0) f = 0;  // int32
        else if (c1 == 0) f = 2;                   // float32
        else f = 1;                                // uint8
        g_mask_flag = f;
    }
}

__device__ __forceinline__ bool mask_valid(const void* m, int idx, int flag) {
    if (flag == 1) return ((const unsigned char*)m)[idx] != 0;
    if (flag == 2) return ((const float*)m)[idx] != 0.0f;
    return ((const int*)m)[idx] != 0;
}

// ---------------- split fp32 -> bf16 hi/lo ----------------
__global__ void __launch_bounds__(256) split_kernel(
    const float* __restrict__ x, __nv_bfloat16* __restrict__ hi,
    __nv_bfloat16* __restrict__ lo, size_t n)
{
    size_t i = ((size_t)blockIdx.x * 256 + threadIdx.x) * 4;
    if (i >= n) return;
    float4 v = *(const float4*)(x + i);
    __nv_bfloat16 h0 = __float2bfloat16_rn(v.x);
    __nv_bfloat16 h1 = __float2bfloat16_rn(v.y);
    __nv_bfloat16 h2 = __float2bfloat16_rn(v.z);
    __nv_bfloat16 h3 = __float2bfloat16_rn(v.w);
    __nv_bfloat162* hp = (__nv_bfloat162*)(hi + i);
    hp[0] = __nv_bfloat162(h0, h1);
    hp[1] = __nv_bfloat162(h2, h3);
    __nv_bfloat162* lp = (__nv_bfloat162*)(lo + i);
    lp[0] = __nv_bfloat162(__float2bfloat16_rn(v.x - __bfloat162float(h0)),
                           __float2bfloat16_rn(v.y - __bfloat162float(h1)));
    lp[1] = __nv_bfloat162(__float2bfloat16_rn(v.z - __bfloat162float(h2)),
                           __float2bfloat16_rn(v.w - __bfloat162float(h3)));
}

// ---------------- layernorm -> split bf16 hi/lo ----------------
__global__ void __launch_bounds__(256) ln_split_kernel(
    const float* __restrict__ x, const float* __restrict__ w,
    const float* __restrict__ b, __nv_bfloat16* __restrict__ hi,
    __nv_bfloat16* __restrict__ lo)
{
    int row = blockIdx.x;
    const float* xr = x + (size_t)row * DDIM;
    float sum = 0.f, sumsq = 0.f;
    for (int i = threadIdx.x; i < DDIM; i += blockDim.x) {
        float v = xr[i]; sum += v; sumsq += v * v;
    }
    __shared__ float s1[32], s2[32];
    for (int o = 16; o; o >>= 1) {
        sum   += __shfl_down_sync(0xffffffffu, sum, o);
        sumsq += __shfl_down_sync(0xffffffffu, sumsq, o);
    }
    int lane = threadIdx.x & 31, wid = threadIdx.x >> 5;
    if (lane == 0) { s1[wid] = sum; s2[wid] = sumsq; }
    __syncthreads();
    if (wid == 0) {
        sum   = lane < 8 ? s1[lane] : 0.f;
        sumsq = lane < 8 ? s2[lane] : 0.f;
        for (int o = 4; o; o >>= 1) {
            sum   += __shfl_down_sync(0xffffffffu, sum, o);
            sumsq += __shfl_down_sync(0xffffffffu, sumsq, o);
        }
        if (lane == 0) { s1[0] = sum; s2[0] = sumsq; }
    }
    __syncthreads();
    float mu  = s1[0] * (1.0f / DDIM);
    float var = s2[0] * (1.0f / DDIM) - mu * mu;
    float inv = rsqrtf(var + 1e-5f);
    size_t base = (size_t)row * DDIM;
    for (int i = threadIdx.x; i < DDIM; i += blockDim.x) {
        float v = (xr[i] - mu) * inv * w[i] + b[i];
        __nv_bfloat16 h = __float2bfloat16_rn(v);
        hi[base + i] = h;
        lo[base + i] = __float2bfloat16_rn(v - __bfloat162float(h));
    }
}

// ---------------- tensor-core split-bf16 GEMM ----------------
// C[M,N] = A[M,K] * W[N,K]^T using C = Ah*Bh + Al*Bh + Ah*Bl (fp32 accum)
// block 128x128, BK=32, 256 threads, warp grid 2(m) x 4(n), warp tile 64x32
#define GS 40   // smem row stride in bf16 (80B, conflict-free frag loads)

__device__ __forceinline__ float gelu_exact(float v) {
    return 0.5f * v * (1.0f + erff(v * 0.70710678118654752f));
}

__device__ __forceinline__ void mma_bf16(float* c, const uint32_t* a, uint32_t b0, uint32_t b1) {
    asm volatile(
        "mma.sync.aligned.m16n8k16.row.col.f32.bf16.bf16.f32 "
        "{%0,%1,%2,%3}, {%4,%5,%6,%7}, {%8,%9}, {%0,%1,%2,%3};\n"
        : "+f"(c[0]), "+f"(c[1]), "+f"(c[2]), "+f"(c[3])
        : "r"(a[0]), "r"(a[1]), "r"(a[2]), "r"(a[3]), "r"(b0), "r"(b1));
}

__device__ __forceinline__ void ldsm_x4(uint32_t* r, uint32_t addr) {
    asm volatile("ldmatrix.sync.aligned.m8n8.x4.shared.b16 {%0,%1,%2,%3}, [%4];\n"
                 : "=r"(r[0]), "=r"(r[1]), "=r"(r[2]), "=r"(r[3]) : "r"(addr));
}

__global__ void __launch_bounds__(256) gemm_bf3_kernel(
    const __nv_bfloat16* __restrict__ Ah, const __nv_bfloat16* __restrict__ Al,
    const __nv_bfloat16* __restrict__ Wh, const __nv_bfloat16* __restrict__ Wl,
    const float* __restrict__ bias, const float* __restrict__ resid,
    float* __restrict__ Cf, __nv_bfloat16* __restrict__ Ch, __nv_bfloat16* __restrict__ Cl,
    int Kd, int N, int act)
{
    __shared__ __nv_bfloat16 sAh[128*GS], sAl[128*GS], sBh[128*GS], sBl[128*GS];
    const int tid = threadIdx.x;
    const int lane = tid & 31;
    const int warp = tid >> 5;
    const int wm = warp >> 2, wn = warp & 3;
    const size_t bm = (size_t)blockIdx.y * 128, bn = (size_t)blockIdx.x * 128;

    // gmem staging: each thread owns row tid/2, 16 bf16 starting at (tid&1)*16
    const int lrow = tid >> 1;
    const int lseg = (tid & 1) * 16;
    const __nv_bfloat16* gAh = Ah + (bm + lrow) * (size_t)Kd + lseg;
    const __nv_bfloat16* gAl = Al + (bm + lrow) * (size_t)Kd + lseg;
    const __nv_bfloat16* gBh = Wh + (bn + lrow) * (size_t)Kd + lseg;
    const __nv_bfloat16* gBl = Wl + (bn + lrow) * (size_t)Kd + lseg;
    const int soff = lrow * GS + lseg;

    const uint32_t aBaseH = (uint32_t)__cvta_generic_to_shared(sAh);
    const uint32_t aBaseL = (uint32_t)__cvta_generic_to_shared(sAl);
    const int arow = wm * 64 + (lane & 15);
    const int acol = (lane >> 4) << 3;
    const int bg = lane >> 2;          // n within 8
    const int bt = (lane & 3) << 1;    // k pair

    float acc[4][4][4];
#pragma unroll
    for (int i = 0; i < 4; i++)
#pragma unroll
        for (int j = 0; j < 4; j++)
#pragma unroll
            for (int t = 0; t < 4; t++) acc[i][j][t] = 0.f;

    uint4 pAh0 = *(const uint4*)(gAh),     pAh1 = *(const uint4*)(gAh + 8);
    uint4 pAl0 = *(const uint4*)(gAl),     pAl1 = *(const uint4*)(gAl + 8);
    uint4 pBh0 = *(const uint4*)(gBh),     pBh1 = *(const uint4*)(gBh + 8);
    uint4 pBl0 = *(const uint4*)(gBl),     pBl1 = *(const uint4*)(gBl + 8);

    for (int k0 = 0; k0 < Kd; k0 += 32) {
        *(uint4*)&sAh[soff] = pAh0; *(uint4*)&sAh[soff + 8] = pAh1;
        *(uint4*)&sAl[soff] = pAl0; *(uint4*)&sAl[soff + 8] = pAl1;
        *(uint4*)&sBh[soff] = pBh0; *(uint4*)&sBh[soff + 8] = pBh1;
        *(uint4*)&sBl[soff] = pBl0; *(uint4*)&sBl[soff + 8] = pBl1;
        __syncthreads();
        if (k0 + 32 < Kd) {
            pAh0 = *(const uint4*)(gAh + k0 + 32); pAh1 = *(const uint4*)(gAh + k0 + 40);
            pAl0 = *(const uint4*)(gAl + k0 + 32); pAl1 = *(const uint4*)(gAl + k0 + 40);
            pBh0 = *(const uint4*)(gBh + k0 + 32); pBh1 = *(const uint4*)(gBh + k0 + 40);
            pBl0 = *(const uint4*)(gBl + k0 + 32); pBl1 = *(const uint4*)(gBl + k0 + 40);
        }
#pragma unroll
        for (int ks = 0; ks < 32; ks += 16) {
            uint32_t afh[4][4], afl[4][4];
#pragma unroll
            for (int mi = 0; mi < 4; mi++) {
                uint32_t off = (uint32_t)(((arow + mi * 16) * GS + ks + acol) * 2);
                ldsm_x4(afh[mi], aBaseH + off);
                ldsm_x4(afl[mi], aBaseL + off);
            }
#pragma unroll
            for (int ni = 0; ni < 4; ni++) {
                int bidx = (wn * 32 + ni * 8 + bg) * GS + ks + bt;
                uint32_t bh0 = *(const uint32_t*)&sBh[bidx];
                uint32_t bh1 = *(const uint32_t*)&sBh[bidx + 8];
                uint32_t bl0 = *(const uint32_t*)&sBl[bidx];
                uint32_t bl1 = *(const uint32_t*)&sBl[bidx + 8];
#pragma unroll
                for (int mi = 0; mi < 4; mi++) {
                    mma_bf16(acc[mi][ni], afh[mi], bh0, bh1);
                    mma_bf16(acc[mi][ni], afl[mi], bh0, bh1);
                    mma_bf16(acc[mi][ni], afh[mi], bl0, bl1);
                }
            }
        }
        __syncthreads();
    }

    // epilogue
    const int gr = lane >> 2;
    const int gc = (lane & 3) << 1;
#pragma unroll
    for (int mi = 0; mi < 4; mi++) {
        size_t r0 = bm + wm * 64 + mi * 16 + gr;
#pragma unroll
        for (int ni = 0; ni < 4; ni++) {
            size_t c0 = bn + wn * 32 + ni * 8 + gc;
            float bv0 = bias ? bias[c0] : 0.f;
            float bv1 = bias ? bias[c0 + 1] : 0.f;
#pragma unroll
            for (int half = 0; half < 2; half++) {
                size_t row = r0 + half * 8;
                float v0 = acc[mi][ni][half * 2 + 0] + bv0;
                float v1 = acc[mi][ni][half * 2 + 1] + bv1;
                if (resid) {
                    v0 += resid[row * N + c0];
                    v1 += resid[row * N + c0 + 1];
                }
                if (act) { v0 = gelu_exact(v0); v1 = gelu_exact(v1); }
                if (Cf) {
                    Cf[row * N + c0]     = v0;
                    Cf[row * N + c0 + 1] = v1;
                }
                if (Ch) {
                    __nv_bfloat16 h0 = __float2bfloat16_rn(v0);
                    __nv_bfloat16 h1 = __float2bfloat16_rn(v1);
                    Ch[row * N + c0]     = h0;
                    Ch[row * N + c0 + 1] = h1;
                    Cl[row * N + c0]     = __float2bfloat16_rn(v0 - __bfloat162float(h0));
                    Cl[row * N + c0 + 1] = __float2bfloat16_rn(v1 - __bfloat162float(h1));
                }
            }
        }
    }
}

// ---------------- batched scores: S[b,h,q,k] = scale * <q,k> (fp32) ----------------
__global__ void __launch_bounds__(256) scores_kernel(
    const float* __restrict__ qb, const float* __restrict__ kb, float* __restrict__ S)
{
    int z = blockIdx.z;
    int b = z / NH, h = z % NH;
    const float* A = qb + (size_t)b * QQL * DDIM + h * HDIM;
    const float* W = kb + (size_t)b * KKL * DDIM + h * HDIM;
    float* C = S + (size_t)z * QQL * KKL;

    __shared__ float As[16][68];
    __shared__ float Bs[16][68];
    int bm = blockIdx.y * 64, bn = blockIdx.x * 64;
    int tid = threadIdx.x;
    int tx = tid & 15, ty = tid >> 4;
    int lr = tid >> 2;
    int lk = (tid & 3) * 4;
    const float* Ap = A + (size_t)(bm + lr) * DDIM + lk;
    const float* Wp = W + (size_t)(bn + lr) * DDIM + lk;
    float acc[4][4] = {};
#pragma unroll
    for (int k0 = 0; k0 < HDIM; k0 += 16) {
        float4 a = *(const float4*)(Ap + k0);
        float4 w = *(const float4*)(Wp + k0);
        __syncthreads();
        As[lk + 0][lr] = a.x; As[lk + 1][lr] = a.y; As[lk + 2][lr] = a.z; As[lk + 3][lr] = a.w;
        Bs[lk + 0][lr] = w.x; Bs[lk + 1][lr] = w.y; Bs[lk + 2][lr] = w.z; Bs[lk + 3][lr] = w.w;
        __syncthreads();
#pragma unroll
        for (int kk = 0; kk < 16; kk++) {
            float4 av = *(const float4*)&As[kk][ty * 4];
            float4 bv = *(const float4*)&Bs[kk][tx * 4];
            acc[0][0] += av.x * bv.x; acc[0][1] += av.x * bv.y; acc[0][2] += av.x * bv.z; acc[0][3] += av.x * bv.w;
            acc[1][0] += av.y * bv.x; acc[1][1] += av.y * bv.y; acc[1][2] += av.y * bv.z; acc[1][3] += av.y * bv.w;
            acc[2][0] += av.z * bv.x; acc[2][1] += av.z * bv.y; acc[2][2] += av.z * bv.z; acc[2][3] += av.z * bv.w;
            acc[3][0] += av.w * bv.x; acc[3][1] += av.w * bv.y; acc[3][2] += av.w * bv.z; acc[3][3] += av.w * bv.w;
        }
    }
    const float scale = 0.125f;
#pragma unroll
    for (int i = 0; i < 4; i++) {
        int m = bm + ty * 4 + i;
#pragma unroll
        for (int j = 0; j < 4; j++) {
            int n = bn + tx * 4 + j;
            C[(size_t)m * KKL + n] = acc[i][j] * scale;
        }
    }
}

// ---------------- masked softmax over K (in place) ----------------
__global__ void __launch_bounds__(256) softmax_kernel(float* __restrict__ S, const void* __restrict__ mask)
{
    size_t row = blockIdx.x;
    int b = (int)(row / ((size_t)NH * QQL));
    float* r = S + row * (size_t)KKL;
    int flag = g_mask_flag;
    int t = threadIdx.x;

    float vals[4];
    float mx = -1e30f;
#pragma unroll
    for (int i = 0; i < 4; i++) {
        int k = t + i * 256;
        bool valid = mask_valid(mask, b * KKL + k, flag);
        float v = valid ? r[k] : -__int_as_float(0x7f800000);
        vals[i] = v;
        mx = fmaxf(mx, v);
    }
    __shared__ float red[256];
    red[t] = mx; __syncthreads();
    for (int s = 128; s; s >>= 1) { if (t < s) red[t] = fmaxf(red[t], red[t + s]); __syncthreads(); }
    mx = red[0]; __syncthreads();

    float sum = 0.f;
#pragma unroll
    for (int i = 0; i < 4; i++) {
        float e = expf(vals[i] - mx);
        vals[i] = e;
        sum += e;
    }
    red[t] = sum; __syncthreads();
    for (int s = 128; s; s >>= 1) { if (t < s) red[t] += red[t + s]; __syncthreads(); }
    float inv = 1.0f / red[0];
#pragma unroll
    for (int i = 0; i < 4; i++)
        r[t + i * 256] = vals[i] * inv;
}

// ---------------- mean over heads ----------------
__global__ void __launch_bounds__(256) mean_heads_kernel(const float* __restrict__ attn, float* __restrict__ out)
{
    size_t idx = (size_t)blockIdx.x * blockDim.x + threadIdx.x;
    if (idx >= (size_t)BB * QQL * KKL) return;
    int k = (int)(idx % KKL);
    size_t t = idx / KKL;
    int q = (int)(t % QQL);
    int b = (int)(t / QQL);
    float s = 0.f;
#pragma unroll
    for (int h = 0; h < NH; h++)
        s += attn[(((size_t)b * NH + h) * QQL + q) * KKL + k];
    out[idx] = s * (1.0f / NH);
}

// ---------------- batched NN: out = attn @ V (fp32) ----------------
__global__ void __launch_bounds__(256) av_kernel(
    const float* __restrict__ attn, const float* __restrict__ vb, float* __restrict__ out)
{
    int z = blockIdx.z;
    int b = z / NH, h = z % NH;
    const float* A = attn + (size_t)z * QQL * KKL;
    const float* Bm = vb + (size_t)b * KKL * DDIM + h * HDIM;
    float* C = out + (size_t)b * QQL * DDIM + h * HDIM;

    __shared__ float As[16][68];
    __shared__ float Bs[16][68];
    int bm = blockIdx.y * 64;
    int tid = threadIdx.x;
    int tx = tid & 15, ty = tid >> 4;
    int lr = tid >> 2;
    int lk = (tid & 3) * 4;
    int brow = tid >> 4;
    int bcol = (tid & 15) * 4;
    const float* Ap = A + (size_t)(bm + lr) * KKL + lk;
    float acc[4][4] = {};
    for (int k0 = 0; k0 < KKL; k0 += 16) {
        float4 a = *(const float4*)(Ap + k0);
        float4 w = *(const float4*)(Bm + (size_t)(k0 + brow) * DDIM + bcol);
        __syncthreads();
        As[lk + 0][lr] = a.x; As[lk + 1][lr] = a.y; As[lk + 2][lr] = a.z; As[lk + 3][lr] = a.w;
        *(float4*)&Bs[brow][bcol] = w;
        __syncthreads();
#pragma unroll
        for (int kk = 0; kk < 16; kk++) {
            float4 av = *(const float4*)&As[kk][ty * 4];
            float4 bv = *(const float4*)&Bs[kk][tx * 4];
            acc[0][0] += av.x * bv.x; acc[0][1] += av.x * bv.y; acc[0][2] += av.x * bv.z; acc[0][3] += av.x * bv.w;
            acc[1][0] += av.y * bv.x; acc[1][1] += av.y * bv.y; acc[1][2] += av.y * bv.z; acc[1][3] += av.y * bv.w;
            acc[2][0] += av.z * bv.x; acc[2][1] += av.z * bv.y; acc[2][2] += av.z * bv.z; acc[2][3] += av.z * bv.w;
            acc[3][0] += av.w * bv.x; acc[3][1] += av.w * bv.y; acc[3][2] += av.w * bv.z; acc[3][3] += av.w * bv.w;
        }
    }
#pragma unroll
    for (int i = 0; i < 4; i++) {
        int m = bm + ty * 4 + i;
#pragma unroll
        for (int j = 0; j < 4; j++) {
            int n = tx * 4 + j;
            C[(size_t)m * DDIM + n] = acc[i][j];
        }
    }
}

// ---------------- launch ----------------
extern "C" void kernel_launch(void* const* d_in, const int* in_sizes, int n_in,
                              void* d_out, int out_size)
{
    const float* query      = (const float*)d_in[0];
    const float* key_value  = (const float*)d_in[1];
    const void*  kpm        = d_in[2];
    const float* ln_q_w     = (const float*)d_in[3];
    const float* ln_q_b     = (const float*)d_in[4];
    const float* ln_kv_w    = (const float*)d_in[5];
    const float* ln_kv_b    = (const float*)d_in[6];
    const float* ln_f_w     = (const float*)d_in[7];
    const float* ln_f_b     = (const float*)d_in[8];
    const float* in_proj_w  = (const float*)d_in[9];
    const float* in_proj_b  = (const float*)d_in[10];
    const float* out_proj_w = (const float*)d_in[11];
    const float* out_proj_b = (const float*)d_in[12];
    const float* ffn_w1     = (const float*)d_in[13];
    const float* ffn_b1     = (const float*)d_in[14];
    const float* ffn_w2     = (const float*)d_in[15];
    const float* ffn_b2     = (const float*)d_in[16];

    float* out_x    = (float*)d_out;
    float* out_attn = out_x + (size_t)BB * QQL * DDIM;

    __nv_bfloat16 *qnh, *qnl, *kvnh, *kvnl, *lnfh, *lnfl, *aoh, *aol, *hh, *hl, *wh, *wl;
    float *qp, *kp, *vp, *sc, *ao, *xb;
    cudaGetSymbolAddress((void**)&qnh,  g_qn_h);  cudaGetSymbolAddress((void**)&qnl,  g_qn_l);
    cudaGetSymbolAddress((void**)&kvnh, g_kvn_h); cudaGetSymbolAddress((void**)&kvnl, g_kvn_l);
    cudaGetSymbolAddress((void**)&lnfh, g_lnf_h); cudaGetSymbolAddress((void**)&lnfl, g_lnf_l);
    cudaGetSymbolAddress((void**)&aoh,  g_ao_h);  cudaGetSymbolAddress((void**)&aol,  g_ao_l);
    cudaGetSymbolAddress((void**)&hh,   g_hh);    cudaGetSymbolAddress((void**)&hl,   g_hl);
    cudaGetSymbolAddress((void**)&wh,   g_w_h);   cudaGetSymbolAddress((void**)&wl,   g_w_l);
    cudaGetSymbolAddress((void**)&qp,   g_q);
    cudaGetSymbolAddress((void**)&kp,   g_k);
    cudaGetSymbolAddress((void**)&vp,   g_v);
    cudaGetSymbolAddress((void**)&sc,   g_scores);
    cudaGetSymbolAddress((void**)&ao,   g_attnout);
    cudaGetSymbolAddress((void**)&xb,   g_x);

    const size_t M1 = (size_t)1024 * 1024;
    const size_t OFF_INPROJ = 0;
    const size_t OFF_OUT    = 3 * M1;
    const size_t OFF_FFN1   = 4 * M1;
    const size_t OFF_FFN2   = 8 * M1;

    detect_mask_kernel<<<1, 256>>>((const unsigned char*)kpm);

    // weight splits
    split_kernel<<<(unsigned)(3 * M1 / 1024), 256>>>(in_proj_w,  wh + OFF_INPROJ, wl + OFF_INPROJ, 3 * M1);
    split_kernel<<<(unsigned)(1 * M1 / 1024), 256>>>(out_proj_w, wh + OFF_OUT,    wl + OFF_OUT,    1 * M1);
    split_kernel<<<(unsigned)(4 * M1 / 1024), 256>>>(ffn_w1,     wh + OFF_FFN1,   wl + OFF_FFN1,   4 * M1);
    split_kernel<<<(unsigned)(4 * M1 / 1024), 256>>>(ffn_w2,     wh + OFF_FFN2,   wl + OFF_FFN2,   4 * M1);

    // layernorms (fused split output)
    ln_split_kernel<<<MROWS, 256>>>(query,     ln_q_w,  ln_q_b,  qnh,  qnl);
    ln_split_kernel<<<MROWS, 256>>>(key_value, ln_kv_w, ln_kv_b, kvnh, kvnl);

    // projections (tensor core)
    dim3 g1024(DDIM / 128, MROWS / 128);
    gemm_bf3_kernel<<<g1024, 256>>>(qnh,  qnl,  wh + OFF_INPROJ,          wl + OFF_INPROJ,          in_proj_b,            nullptr, qp, nullptr, nullptr, DDIM, DDIM, 0);
    gemm_bf3_kernel<<<g1024, 256>>>(kvnh, kvnl, wh + OFF_INPROJ + M1,     wl + OFF_INPROJ + M1,     in_proj_b + DDIM,     nullptr, kp, nullptr, nullptr, DDIM, DDIM, 0);
    gemm_bf3_kernel<<<g1024, 256>>>(kvnh, kvnl, wh + OFF_INPROJ + 2 * M1, wl + OFF_INPROJ + 2 * M1, in_proj_b + 2 * DDIM, nullptr, vp, nullptr, nullptr, DDIM, DDIM, 0);

    // attention (fp32)
    dim3 gsc(KKL / 64, QQL / 64, BB * NH);
    scores_kernel<<<gsc, 256>>>(qp, kp, sc);
    softmax_kernel<<<BB * NH * QQL, 256>>>(sc, kpm);
    mean_heads_kernel<<<(BB * QQL * KKL) / 256, 256>>>(sc, out_attn);
    dim3 gav(1, QQL / 64, BB * NH);
    av_kernel<<<gav, 256>>>(sc, vp, ao);

    // out_proj + residual  -> xb
    split_kernel<<<(unsigned)((size_t)MROWS * DDIM / 1024), 256>>>(ao, aoh, aol, (size_t)MROWS * DDIM);
    gemm_bf3_kernel<<<g1024, 256>>>(aoh, aol, wh + OFF_OUT, wl + OFF_OUT, out_proj_b, query, xb, nullptr, nullptr, DDIM, DDIM, 0);

    // final LN -> FFN
    ln_split_kernel<<<MROWS, 256>>>(xb, ln_f_w, ln_f_b, lnfh, lnfl);

    dim3 gff1(FFD / 128, MROWS / 128);
    gemm_bf3_kernel<<<gff1, 256>>>(lnfh, lnfl, wh + OFF_FFN1, wl + OFF_FFN1, ffn_b1, nullptr, nullptr, hh, hl, DDIM, FFD, 1);

    gemm_bf3_kernel<<<g1024, 256>>>(hh, hl, wh + OFF_FFN2, wl + OFF_FFN2, ffn_b2, xb, out_x, nullptr, nullptr, FFD, DDIM, 0);
}

// round 5
// speedup vs baseline: 2.0223x; 1.0374x over previous
#include <cuda_runtime.h>
#include <cuda_bf16.h>
#include <math.h>
#include <stdint.h>

#define BB 8
#define QQL 1024
#define KKL 1024
#define DDIM 1024
#define NH 16
#define HDIM 64
#define FFD 4096
#define MROWS (BB*QQL)   /* 8192 */
#define GS 40            /* smem row stride (bf16 elems) */

// ---------------- scratch (device globals) ----------------
__device__ __nv_bfloat16 g_qn_h[(size_t)MROWS * DDIM],  g_qn_l[(size_t)MROWS * DDIM];
__device__ __nv_bfloat16 g_kvn_h[(size_t)MROWS * DDIM], g_kvn_l[(size_t)MROWS * DDIM];
__device__ __nv_bfloat16 g_lnf_h[(size_t)MROWS * DDIM], g_lnf_l[(size_t)MROWS * DDIM];
__device__ __nv_bfloat16 g_qp_h[(size_t)MROWS * DDIM],  g_qp_l[(size_t)MROWS * DDIM];
__device__ __nv_bfloat16 g_kp_h[(size_t)MROWS * DDIM],  g_kp_l[(size_t)MROWS * DDIM];
__device__ __nv_bfloat16 g_vt_h[(size_t)MROWS * DDIM],  g_vt_l[(size_t)MROWS * DDIM];
__device__ __nv_bfloat16 g_ao_h[(size_t)MROWS * DDIM],  g_ao_l[(size_t)MROWS * DDIM];
__device__ __nv_bfloat16 g_hh[(size_t)MROWS * FFD],     g_hl[(size_t)MROWS * FFD];
__device__ __nv_bfloat16 g_w_h[(size_t)12 * 1024 * 1024], g_w_l[(size_t)12 * 1024 * 1024];
__device__ __nv_bfloat16 g_attn_h[(size_t)BB * NH * QQL * KKL];   // 256 MB
__device__ __nv_bfloat16 g_attn_l[(size_t)BB * NH * QQL * KKL];   // 256 MB
__device__ float g_v[(size_t)MROWS * DDIM];
__device__ float g_scores[(size_t)BB * NH * QQL * KKL];           // 512 MB
__device__ float g_x[(size_t)MROWS * DDIM];
__device__ int   g_mask_flag;

// ---------------- mask dtype sniffing ----------------
__global__ void detect_mask_kernel(const unsigned char* __restrict__ m) {
    __shared__ int c1, c2, c3;
    if (threadIdx.x == 0) { c1 = 0; c2 = 0; c3 = 0; }
    __syncthreads();
    for (int i = threadIdx.x; i < BB * KKL; i += blockDim.x) {
        unsigned char v = m[i];
        if (v) {
            int p = i & 3;
            if (p == 1) atomicAdd(&c1, 1);
            else if (p == 2) atomicAdd(&c2, 1);
            else if (p == 3) atomicAdd(&c3, 1);
        }
    }
    __syncthreads();
    if (threadIdx.x == 0) {
        int f;
        if (c1 == 0 && c2 == 0 && c3 == 0) f = 0;  // int32
        else if (c1 == 0) f = 2;                   // float32
        else f = 1;                                // uint8
        g_mask_flag = f;
    }
}

__device__ __forceinline__ bool mask_valid(const void* m, int idx, int flag) {
    if (flag == 1) return ((const unsigned char*)m)[idx] != 0;
    if (flag == 2) return ((const float*)m)[idx] != 0.0f;
    return ((const int*)m)[idx] != 0;
}

// ---------------- split fp32 -> bf16 hi/lo ----------------
__global__ void __launch_bounds__(256) split_kernel(
    const float* __restrict__ x, __nv_bfloat16* __restrict__ hi,
    __nv_bfloat16* __restrict__ lo, size_t n)
{
    size_t i = ((size_t)blockIdx.x * 256 + threadIdx.x) * 4;
    if (i >= n) return;
    float4 v = *(const float4*)(x + i);
    __nv_bfloat16 h0 = __float2bfloat16_rn(v.x);
    __nv_bfloat16 h1 = __float2bfloat16_rn(v.y);
    __nv_bfloat16 h2 = __float2bfloat16_rn(v.z);
    __nv_bfloat16 h3 = __float2bfloat16_rn(v.w);
    __nv_bfloat162* hp = (__nv_bfloat162*)(hi + i);
    hp[0] = __nv_bfloat162(h0, h1);
    hp[1] = __nv_bfloat162(h2, h3);
    __nv_bfloat162* lp = (__nv_bfloat162*)(lo + i);
    lp[0] = __nv_bfloat162(__float2bfloat16_rn(v.x - __bfloat162float(h0)),
                           __float2bfloat16_rn(v.y - __bfloat162float(h1)));
    lp[1] = __nv_bfloat162(__float2bfloat16_rn(v.z - __bfloat162float(h2)),
                           __float2bfloat16_rn(v.w - __bfloat162float(h3)));
}

// ---------------- layernorm -> split bf16 hi/lo ----------------
__global__ void __launch_bounds__(256) ln_split_kernel(
    const float* __restrict__ x, const float* __restrict__ w,
    const float* __restrict__ b, __nv_bfloat16* __restrict__ hi,
    __nv_bfloat16* __restrict__ lo)
{
    int row = blockIdx.x;
    const float* xr = x + (size_t)row * DDIM;
    float sum = 0.f, sumsq = 0.f;
    for (int i = threadIdx.x; i < DDIM; i += blockDim.x) {
        float v = xr[i]; sum += v; sumsq += v * v;
    }
    __shared__ float s1[32], s2[32];
    for (int o = 16; o; o >>= 1) {
        sum   += __shfl_down_sync(0xffffffffu, sum, o);
        sumsq += __shfl_down_sync(0xffffffffu, sumsq, o);
    }
    int lane = threadIdx.x & 31, wid = threadIdx.x >> 5;
    if (lane == 0) { s1[wid] = sum; s2[wid] = sumsq; }
    __syncthreads();
    if (wid == 0) {
        sum   = lane < 8 ? s1[lane] : 0.f;
        sumsq = lane < 8 ? s2[lane] : 0.f;
        for (int o = 4; o; o >>= 1) {
            sum   += __shfl_down_sync(0xffffffffu, sum, o);
            sumsq += __shfl_down_sync(0xffffffffu, sumsq, o);
        }
        if (lane == 0) { s1[0] = sum; s2[0] = sumsq; }
    }
    __syncthreads();
    float mu  = s1[0] * (1.0f / DDIM);
    float var = s2[0] * (1.0f / DDIM) - mu * mu;
    float inv = rsqrtf(var + 1e-5f);
    size_t base = (size_t)row * DDIM;
    for (int i = threadIdx.x; i < DDIM; i += blockDim.x) {
        float v = (xr[i] - mu) * inv * w[i] + b[i];
        __nv_bfloat16 h = __float2bfloat16_rn(v);
        hi[base + i] = h;
        lo[base + i] = __float2bfloat16_rn(v - __bfloat162float(h));
    }
}

// ---------------- tensor-core GEMM building blocks ----------------
__device__ __forceinline__ float gelu_exact(float v) {
    return 0.5f * v * (1.0f + erff(v * 0.70710678118654752f));
}

__device__ __forceinline__ void mma_bf16(float* c, const uint32_t* a, uint32_t b0, uint32_t b1) {
    asm volatile(
        "mma.sync.aligned.m16n8k16.row.col.f32.bf16.bf16.f32 "
        "{%0,%1,%2,%3}, {%4,%5,%6,%7}, {%8,%9}, {%0,%1,%2,%3};\n"
        : "+f"(c[0]), "+f"(c[1]), "+f"(c[2]), "+f"(c[3])
        : "r"(a[0]), "r"(a[1]), "r"(a[2]), "r"(a[3]), "r"(b0), "r"(b1));
}

__device__ __forceinline__ void ldsm_x4(uint32_t* r, uint32_t addr) {
    asm volatile("ldmatrix.sync.aligned.m8n8.x4.shared.b16 {%0,%1,%2,%3}, [%4];\n"
                 : "=r"(r[0]), "=r"(r[1]), "=r"(r[2]), "=r"(r[3]) : "r"(addr));
}

// ---------------- unified split-bf16 GEMM (1-pass or 3-pass), optional batch ----------------
// C[M,N] = A[M,K]*W[N,K]^T ; batch z decomposed as (zb, zh) with strides
// block 128x128, BK=32, 256 threads, warps 2(m) x 4(n), warp tile 64x32
__global__ void __launch_bounds__(256) gemm3_kernel(
    const __nv_bfloat16* __restrict__ Ah, const __nv_bfloat16* __restrict__ Al,
    long lda, long sAb, long sAhh,
    const __nv_bfloat16* __restrict__ Wh, const __nv_bfloat16* __restrict__ Wl,
    long ldb, long sBb, long sBhh,
    const float* __restrict__ bias, const float* __restrict__ resid,
    float* __restrict__ Cf, __nv_bfloat16* __restrict__ Ch, __nv_bfloat16* __restrict__ Cl,
    long ldc, long sCb, long sChh,
    int Kd, float scale, int act, int three)
{
    __shared__ __nv_bfloat16 sAhm[128*GS], sAlm[128*GS], sBhm[128*GS], sBlm[128*GS];
    const int tid = threadIdx.x;
    const int lane = tid & 31;
    const int warp = tid >> 5;
    const int wm = warp >> 2, wn = warp & 3;
    const int zb = blockIdx.z / NH, zh = blockIdx.z % NH;
    const size_t Aoff = (size_t)zb * sAb + (size_t)zh * sAhh;
    const size_t Boff = (size_t)zb * sBb + (size_t)zh * sBhh;
    const size_t Coff = (size_t)zb * sCb + (size_t)zh * sChh;
    const size_t bm = (size_t)blockIdx.y * 128, bn = (size_t)blockIdx.x * 128;

    const int lrow = tid >> 1;
    const int lseg = (tid & 1) * 16;
    const __nv_bfloat16* gAh = Ah + Aoff + (bm + lrow) * (size_t)lda + lseg;
    const __nv_bfloat16* gAl = Al + Aoff + (bm + lrow) * (size_t)lda + lseg;
    const __nv_bfloat16* gBh = Wh + Boff + (bn + lrow) * (size_t)ldb + lseg;
    const __nv_bfloat16* gBl = Wl + Boff + (bn + lrow) * (size_t)ldb + lseg;
    const int soff = lrow * GS + lseg;

    const uint32_t aBaseH = (uint32_t)__cvta_generic_to_shared(sAhm);
    const uint32_t aBaseL = (uint32_t)__cvta_generic_to_shared(sAlm);
    const int arow = wm * 64 + (lane & 15);
    const int acol = (lane >> 4) << 3;
    const int bg = lane >> 2;
    const int bt = (lane & 3) << 1;

    float acc[4][4][4];
#pragma unroll
    for (int i = 0; i < 4; i++)
#pragma unroll
        for (int j = 0; j < 4; j++)
#pragma unroll
            for (int t = 0; t < 4; t++) acc[i][j][t] = 0.f;

    uint4 pAh0 = *(const uint4*)(gAh),     pAh1 = *(const uint4*)(gAh + 8);
    uint4 pBh0 = *(const uint4*)(gBh),     pBh1 = *(const uint4*)(gBh + 8);
    uint4 pAl0, pAl1, pBl0, pBl1;
    if (three) {
        pAl0 = *(const uint4*)(gAl); pAl1 = *(const uint4*)(gAl + 8);
        pBl0 = *(const uint4*)(gBl); pBl1 = *(const uint4*)(gBl + 8);
    }

    for (int k0 = 0; k0 < Kd; k0 += 32) {
        *(uint4*)&sAhm[soff] = pAh0; *(uint4*)&sAhm[soff + 8] = pAh1;
        *(uint4*)&sBhm[soff] = pBh0; *(uint4*)&sBhm[soff + 8] = pBh1;
        if (three) {
            *(uint4*)&sAlm[soff] = pAl0; *(uint4*)&sAlm[soff + 8] = pAl1;
            *(uint4*)&sBlm[soff] = pBl0; *(uint4*)&sBlm[soff + 8] = pBl1;
        }
        __syncthreads();
        if (k0 + 32 < Kd) {
            pAh0 = *(const uint4*)(gAh + k0 + 32); pAh1 = *(const uint4*)(gAh + k0 + 40);
            pBh0 = *(const uint4*)(gBh + k0 + 32); pBh1 = *(const uint4*)(gBh + k0 + 40);
            if (three) {
                pAl0 = *(const uint4*)(gAl + k0 + 32); pAl1 = *(const uint4*)(gAl + k0 + 40);
                pBl0 = *(const uint4*)(gBl + k0 + 32); pBl1 = *(const uint4*)(gBl + k0 + 40);
            }
        }
#pragma unroll
        for (int ks = 0; ks < 32; ks += 16) {
            uint32_t afh[4][4], afl[4][4];
#pragma unroll
            for (int mi = 0; mi < 4; mi++) {
                uint32_t off = (uint32_t)(((arow + mi * 16) * GS + ks + acol) * 2);
                ldsm_x4(afh[mi], aBaseH + off);
                if (three) ldsm_x4(afl[mi], aBaseL + off);
            }
#pragma unroll
            for (int ni = 0; ni < 4; ni++) {
                int bidx = (wn * 32 + ni * 8 + bg) * GS + ks + bt;
                uint32_t bh0 = *(const uint32_t*)&sBhm[bidx];
                uint32_t bh1 = *(const uint32_t*)&sBhm[bidx + 8];
#pragma unroll
                for (int mi = 0; mi < 4; mi++)
                    mma_bf16(acc[mi][ni], afh[mi], bh0, bh1);
                if (three) {
                    uint32_t bl0 = *(const uint32_t*)&sBlm[bidx];
                    uint32_t bl1 = *(const uint32_t*)&sBlm[bidx + 8];
#pragma unroll
                    for (int mi = 0; mi < 4; mi++) {
                        mma_bf16(acc[mi][ni], afl[mi], bh0, bh1);
                        mma_bf16(acc[mi][ni], afh[mi], bl0, bl1);
                    }
                }
            }
        }
        __syncthreads();
    }

    const int gr = lane >> 2;
    const int gc = (lane & 3) << 1;
#pragma unroll
    for (int mi = 0; mi < 4; mi++) {
        size_t r0 = bm + wm * 64 + mi * 16 + gr;
#pragma unroll
        for (int ni = 0; ni < 4; ni++) {
            size_t c0 = bn + wn * 32 + ni * 8 + gc;
            float bv0 = bias ? bias[c0] : 0.f;
            float bv1 = bias ? bias[c0 + 1] : 0.f;
#pragma unroll
            for (int half = 0; half < 2; half++) {
                size_t row = r0 + half * 8;
                float v0 = acc[mi][ni][half * 2 + 0] * scale + bv0;
                float v1 = acc[mi][ni][half * 2 + 1] * scale + bv1;
                if (resid) {
                    v0 += resid[Coff + row * ldc + c0];
                    v1 += resid[Coff + row * ldc + c0 + 1];
                }
                if (act) { v0 = gelu_exact(v0); v1 = gelu_exact(v1); }
                size_t o = Coff + row * ldc + c0;
                if (Cf) { Cf[o] = v0; Cf[o + 1] = v1; }
                if (Ch) {
                    __nv_bfloat16 h0 = __float2bfloat16_rn(v0);
                    __nv_bfloat16 h1 = __float2bfloat16_rn(v1);
                    Ch[o] = h0; Ch[o + 1] = h1;
                    Cl[o]     = __float2bfloat16_rn(v0 - __bfloat162float(h0));
                    Cl[o + 1] = __float2bfloat16_rn(v1 - __bfloat162float(h1));
                }
            }
        }
    }
}

// ---------------- transpose + split V: vt[b, c, k] = v[b*1024+k, c] ----------------
__global__ void __launch_bounds__(256) transpose_split_kernel(
    const float* __restrict__ v, __nv_bfloat16* __restrict__ th, __nv_bfloat16* __restrict__ tl)
{
    __shared__ float tile[32][33];
    int tx = threadIdx.x, ty = threadIdx.y;
    int c0 = blockIdx.x * 32;
    int r0 = blockIdx.y * 32;
#pragma unroll
    for (int i = 0; i < 4; i++)
        tile[ty + i * 8][tx] = v[(size_t)(r0 + ty + i * 8) * DDIM + c0 + tx];
    __syncthreads();
    int b = r0 >> 10;
    int kk0 = r0 & 1023;
#pragma unroll
    for (int i = 0; i < 4; i++) {
        float val = tile[tx][ty + i * 8];
        size_t o = ((size_t)(b << 10) + c0 + ty + i * 8) * 1024 + kk0 + tx;
        __nv_bfloat16 h = __float2bfloat16_rn(val);
        th[o] = h;
        tl[o] = __float2bfloat16_rn(val - __bfloat162float(h));
    }
}

// ---------------- masked softmax: fp32 scores -> bf16 hi/lo attn ----------------
__global__ void __launch_bounds__(256) softmax_kernel(
    const float* __restrict__ S, const void* __restrict__ mask,
    __nv_bfloat16* __restrict__ ah, __nv_bfloat16* __restrict__ al)
{
    size_t row = blockIdx.x;
    int b = (int)(row / ((size_t)NH * QQL));
    const float* r = S + row * (size_t)KKL;
    int flag = g_mask_flag;
    int t = threadIdx.x;

    float vals[4];
    float mx = -1e30f;
#pragma unroll
    for (int i = 0; i < 4; i++) {
        int k = t + i * 256;
        bool valid = mask_valid(mask, b * KKL + k, flag);
        float v = valid ? r[k] : -__int_as_float(0x7f800000);
        vals[i] = v;
        mx = fmaxf(mx, v);
    }
    __shared__ float red[256];
    red[t] = mx; __syncthreads();
    for (int s = 128; s; s >>= 1) { if (t < s) red[t] = fmaxf(red[t], red[t + s]); __syncthreads(); }
    mx = red[0]; __syncthreads();

    float sum = 0.f;
#pragma unroll
    for (int i = 0; i < 4; i++) {
        float e = expf(vals[i] - mx);
        vals[i] = e;
        sum += e;
    }
    red[t] = sum; __syncthreads();
    for (int s = 128; s; s >>= 1) { if (t < s) red[t] += red[t + s]; __syncthreads(); }
    float inv = 1.0f / red[0];
    size_t base = row * (size_t)KKL;
#pragma unroll
    for (int i = 0; i < 4; i++) {
        int k = t + i * 256;
        float p = vals[i] * inv;
        __nv_bfloat16 h = __float2bfloat16_rn(p);
        ah[base + k] = h;
        al[base + k] = __float2bfloat16_rn(p - __bfloat162float(h));
    }
}

// ---------------- mean over heads (reads hi+lo) ----------------
__global__ void __launch_bounds__(256) mean_heads_kernel(
    const __nv_bfloat16* __restrict__ ah, const __nv_bfloat16* __restrict__ al,
    float* __restrict__ out)
{
    size_t idx2 = (size_t)blockIdx.x * 256 + threadIdx.x;
    if (idx2 >= (size_t)BB * QQL * KKL / 2) return;
    size_t idx = idx2 * 2;
    int k = (int)(idx % KKL);
    size_t t = idx / KKL;
    int q = (int)(t % QQL);
    int b = (int)(t / QQL);
    float s0 = 0.f, s1 = 0.f;
    size_t base = ((size_t)b * NH * QQL + q) * KKL + k;
#pragma unroll
    for (int h = 0; h < NH; h++) {
        size_t o = base + (size_t)h * QQL * KKL;
        __nv_bfloat162 hv = *(const __nv_bfloat162*)(ah + o);
        __nv_bfloat162 lv = *(const __nv_bfloat162*)(al + o);
        s0 += __bfloat162float(hv.x) + __bfloat162float(lv.x);
        s1 += __bfloat162float(hv.y) + __bfloat162float(lv.y);
    }
    out[idx]     = s0 * (1.0f / NH);
    out[idx + 1] = s1 * (1.0f / NH);
}

// ---------------- AV: ao[b,q,h*64+n] = sum_k attn_h[b,h,q,k] * vt[b,h*64+n,k] (1-pass bf16) ----------------
// block 128(m) x 64(n), warps 2(m) x 4(n): warp tile 64x16
__global__ void __launch_bounds__(256) av_kernel(
    const __nv_bfloat16* __restrict__ attn, const __nv_bfloat16* __restrict__ vt,
    __nv_bfloat16* __restrict__ Ch, __nv_bfloat16* __restrict__ Cl)
{
    __shared__ __nv_bfloat16 sA[128 * GS], sB[64 * GS];
    const int tid = threadIdx.x;
    const int lane = tid & 31;
    const int warp = tid >> 5;
    const int wm = warp >> 2, wn = warp & 3;
    const int z = blockIdx.z;
    const int b = z / NH, h = z % NH;
    const size_t bm = (size_t)blockIdx.y * 128;

    const __nv_bfloat16* A = attn + (size_t)z * QQL * KKL;
    const __nv_bfloat16* W = vt + ((size_t)b * 1024 + h * 64) * 1024;
    const size_t Coff = (size_t)b * QQL * DDIM + h * HDIM;

    const int lrow = tid >> 1;
    const int lseg = (tid & 1) * 16;
    const __nv_bfloat16* gA = A + (bm + lrow) * (size_t)KKL + lseg;
    const int soffA = lrow * GS + lseg;
    const int brow = tid >> 2;
    const int bseg = (tid & 3) * 8;
    const __nv_bfloat16* gB = W + (size_t)brow * 1024 + bseg;
    const int soffB = brow * GS + bseg;

    const uint32_t aBase = (uint32_t)__cvta_generic_to_shared(sA);
    const int arow = wm * 64 + (lane & 15);
    const int acol = (lane >> 4) << 3;
    const int bg = lane >> 2;
    const int bt = (lane & 3) << 1;

    float acc[4][2][4];
#pragma unroll
    for (int i = 0; i < 4; i++)
#pragma unroll
        for (int j = 0; j < 2; j++)
#pragma unroll
            for (int t = 0; t < 4; t++) acc[i][j][t] = 0.f;

    uint4 pA0 = *(const uint4*)(gA), pA1 = *(const uint4*)(gA + 8);
    uint4 pB  = *(const uint4*)(gB);

    for (int k0 = 0; k0 < KKL; k0 += 32) {
        *(uint4*)&sA[soffA] = pA0; *(uint4*)&sA[soffA + 8] = pA1;
        *(uint4*)&sB[soffB] = pB;
        __syncthreads();
        if (k0 + 32 < KKL) {
            pA0 = *(const uint4*)(gA + k0 + 32); pA1 = *(const uint4*)(gA + k0 + 40);
            pB  = *(const uint4*)(gB + k0 + 32);
        }
#pragma unroll
        for (int ks = 0; ks < 32; ks += 16) {
            uint32_t af[4][4];
#pragma unroll
            for (int mi = 0; mi < 4; mi++) {
                uint32_t off = (uint32_t)(((arow + mi * 16) * GS + ks + acol) * 2);
                ldsm_x4(af[mi], aBase + off);
            }
#pragma unroll
            for (int ni = 0; ni < 2; ni++) {
                int bidx = (wn * 16 + ni * 8 + bg) * GS + ks + bt;
                uint32_t b0 = *(const uint32_t*)&sB[bidx];
                uint32_t b1 = *(const uint32_t*)&sB[bidx + 8];
#pragma unroll
                for (int mi = 0; mi < 4; mi++)
                    mma_bf16(acc[mi][ni], af[mi], b0, b1);
            }
        }
        __syncthreads();
    }

    const int gr = lane >> 2;
    const int gc = (lane & 3) << 1;
#pragma unroll
    for (int mi = 0; mi < 4; mi++) {
        size_t r0 = bm + wm * 64 + mi * 16 + gr;
#pragma unroll
        for (int ni = 0; ni < 2; ni++) {
            int c0 = wn * 16 + ni * 8 + gc;
#pragma unroll
            for (int half = 0; half < 2; half++) {
                size_t row = r0 + half * 8;
                float v0 = acc[mi][ni][half * 2 + 0];
                float v1 = acc[mi][ni][half * 2 + 1];
                size_t o = Coff + row * DDIM + c0;
                __nv_bfloat16 h0 = __float2bfloat16_rn(v0);
                __nv_bfloat16 h1 = __float2bfloat16_rn(v1);
                Ch[o] = h0; Ch[o + 1] = h1;
                Cl[o]     = __float2bfloat16_rn(v0 - __bfloat162float(h0));
                Cl[o + 1] = __float2bfloat16_rn(v1 - __bfloat162float(h1));
            }
        }
    }
}

// ---------------- launch ----------------
extern "C" void kernel_launch(void* const* d_in, const int* in_sizes, int n_in,
                              void* d_out, int out_size)
{
    const float* query      = (const float*)d_in[0];
    const float* key_value  = (const float*)d_in[1];
    const void*  kpm        = d_in[2];
    const float* ln_q_w     = (const float*)d_in[3];
    const float* ln_q_b     = (const float*)d_in[4];
    const float* ln_kv_w    = (const float*)d_in[5];
    const float* ln_kv_b    = (const float*)d_in[6];
    const float* ln_f_w     = (const float*)d_in[7];
    const float* ln_f_b     = (const float*)d_in[8];
    const float* in_proj_w  = (const float*)d_in[9];
    const float* in_proj_b  = (const float*)d_in[10];
    const float* out_proj_w = (const float*)d_in[11];
    const float* out_proj_b = (const float*)d_in[12];
    const float* ffn_w1     = (const float*)d_in[13];
    const float* ffn_b1     = (const float*)d_in[14];
    const float* ffn_w2     = (const float*)d_in[15];
    const float* ffn_b2     = (const float*)d_in[16];

    float* out_x    = (float*)d_out;
    float* out_attn = out_x + (size_t)BB * QQL * DDIM;

    __nv_bfloat16 *qnh, *qnl, *kvnh, *kvnl, *lnfh, *lnfl, *aoh, *aol, *hh, *hl, *wh, *wl;
    __nv_bfloat16 *qph, *qpl, *kph, *kpl, *vth, *vtl, *ath, *atl;
    float *vp, *sc, *xb;
    cudaGetSymbolAddress((void**)&qnh,  g_qn_h);  cudaGetSymbolAddress((void**)&qnl,  g_qn_l);
    cudaGetSymbolAddress((void**)&kvnh, g_kvn_h); cudaGetSymbolAddress((void**)&kvnl, g_kvn_l);
    cudaGetSymbolAddress((void**)&lnfh, g_lnf_h); cudaGetSymbolAddress((void**)&lnfl, g_lnf_l);
    cudaGetSymbolAddress((void**)&aoh,  g_ao_h);  cudaGetSymbolAddress((void**)&aol,  g_ao_l);
    cudaGetSymbolAddress((void**)&hh,   g_hh);    cudaGetSymbolAddress((void**)&hl,   g_hl);
    cudaGetSymbolAddress((void**)&wh,   g_w_h);   cudaGetSymbolAddress((void**)&wl,   g_w_l);
    cudaGetSymbolAddress((void**)&qph,  g_qp_h);  cudaGetSymbolAddress((void**)&qpl,  g_qp_l);
    cudaGetSymbolAddress((void**)&kph,  g_kp_h);  cudaGetSymbolAddress((void**)&kpl,  g_kp_l);
    cudaGetSymbolAddress((void**)&vth,  g_vt_h);  cudaGetSymbolAddress((void**)&vtl,  g_vt_l);
    cudaGetSymbolAddress((void**)&ath,  g_attn_h);cudaGetSymbolAddress((void**)&atl,  g_attn_l);
    cudaGetSymbolAddress((void**)&vp,   g_v);
    cudaGetSymbolAddress((void**)&sc,   g_scores);
    cudaGetSymbolAddress((void**)&xb,   g_x);

    const size_t M1 = (size_t)1024 * 1024;
    const size_t OFF_OUT  = 3 * M1;
    const size_t OFF_FFN1 = 4 * M1;
    const size_t OFF_FFN2 = 8 * M1;

    detect_mask_kernel<<<1, 256>>>((const unsigned char*)kpm);

    split_kernel<<<(unsigned)(3 * M1 / 1024), 256>>>(in_proj_w,  wh,            wl,            3 * M1);
    split_kernel<<<(unsigned)(1 * M1 / 1024), 256>>>(out_proj_w, wh + OFF_OUT,  wl + OFF_OUT,  1 * M1);
    split_kernel<<<(unsigned)(4 * M1 / 1024), 256>>>(ffn_w1,     wh + OFF_FFN1, wl + OFF_FFN1, 4 * M1);
    split_kernel<<<(unsigned)(4 * M1 / 1024), 256>>>(ffn_w2,     wh + OFF_FFN2, wl + OFF_FFN2, 4 * M1);

    ln_split_kernel<<<MROWS, 256>>>(query,     ln_q_w,  ln_q_b,  qnh,  qnl);
    ln_split_kernel<<<MROWS, 256>>>(key_value, ln_kv_w, ln_kv_b, kvnh, kvnl);

    dim3 g1024(DDIM / 128, MROWS / 128, 1);
    // q proj (3-pass, bf16 hi/lo out)
    gemm3_kernel<<<g1024, 256>>>(qnh, qnl, DDIM, 0, 0, wh, wl, DDIM, 0, 0,
                                 in_proj_b, nullptr, nullptr, qph, qpl, DDIM, 0, 0,
                                 DDIM, 1.f, 0, 1);
    // k proj (3-pass, bf16 hi/lo out)
    gemm3_kernel<<<g1024, 256>>>(kvnh, kvnl, DDIM, 0, 0, wh + M1, wl + M1, DDIM, 0, 0,
                                 in_proj_b + DDIM, nullptr, nullptr, kph, kpl, DDIM, 0, 0,
                                 DDIM, 1.f, 0, 1);
    // v proj (1-pass, fp32 out)
    gemm3_kernel<<<g1024, 256>>>(kvnh, kvnh, DDIM, 0, 0, wh + 2 * M1, wh + 2 * M1, DDIM, 0, 0,
                                 in_proj_b + 2 * DDIM, nullptr, vp, nullptr, nullptr, DDIM, 0, 0,
                                 DDIM, 1.f, 0, 0);
    transpose_split_kernel<<<dim3(DDIM / 32, MROWS / 32), dim3(32, 8)>>>(vp, vth, vtl);

    // scores (3-pass batched, Kd=64, scale fused)
    dim3 gsc(KKL / 128, QQL / 128, BB * NH);
    gemm3_kernel<<<gsc, 256>>>(qph, qpl, DDIM, (long)QQL * DDIM, HDIM,
                               kph, kpl, DDIM, (long)KKL * DDIM, HDIM,
                               nullptr, nullptr, sc, nullptr, nullptr,
                               KKL, (long)NH * QQL * KKL, (long)QQL * KKL,
                               HDIM, 0.125f, 0, 1);

    softmax_kernel<<<BB * NH * QQL, 256>>>(sc, kpm, ath, atl);
    mean_heads_kernel<<<(BB * QQL * KKL / 2 + 255) / 256, 256>>>(ath, atl, out_attn);

    dim3 gav(1, QQL / 128, BB * NH);
    av_kernel<<<gav, 256>>>(ath, vth, aoh, aol);

    // out_proj + residual (1-pass)
    gemm3_kernel<<<g1024, 256>>>(aoh, aoh, DDIM, 0, 0, wh + OFF_OUT, wh + OFF_OUT, DDIM, 0, 0,
                                 out_proj_b, query, xb, nullptr, nullptr, DDIM, 0, 0,
                                 DDIM, 1.f, 0, 0);

    ln_split_kernel<<<MROWS, 256>>>(xb, ln_f_w, ln_f_b, lnfh, lnfl);

    // ffn1 (3-pass, gelu, bf16 hi/lo out)
    dim3 gff1(FFD / 128, MROWS / 128, 1);
    gemm3_kernel<<<gff1, 256>>>(lnfh, lnfl, DDIM, 0, 0, wh + OFF_FFN1, wl + OFF_FFN1, DDIM, 0, 0,
                                ffn_b1, nullptr, nullptr, hh, hl, FFD, 0, 0,
                                DDIM, 1.f, 1, 1);
    // ffn2 (3-pass, residual, fp32 out)
    gemm3_kernel<<<g1024, 256>>>(hh, hl, FFD, 0, 0, wh + OFF_FFN2, wl + OFF_FFN2, FFD, 0, 0,
                                 ffn_b2, xb, out_x, nullptr, nullptr, DDIM, 0, 0,
                                 FFD, 1.f, 0, 1);
}

// round 6
// speedup vs baseline: 2.8774x; 1.4229x over previous
#include <cuda_runtime.h>
#include <cuda_bf16.h>
#include <math.h>
#include <stdint.h>

#define BB 8
#define QQL 1024
#define KKL 1024
#define DDIM 1024
#define NH 16
#define HDIM 64
#define FFD 4096
#define MROWS (BB*QQL)   /* 8192 */
#define GS 40            /* smem row stride (bf16 elems); 80B => 16B-aligned, ldsm conflict-free */
#define PLANE (128*GS)   /* elems per smem plane */

// ---------------- scratch (device globals) ----------------
__device__ __nv_bfloat16 g_qn_h[(size_t)MROWS * DDIM],  g_qn_l[(size_t)MROWS * DDIM];
__device__ __nv_bfloat16 g_kvn_h[(size_t)MROWS * DDIM], g_kvn_l[(size_t)MROWS * DDIM];
__device__ __nv_bfloat16 g_lnf_h[(size_t)MROWS * DDIM], g_lnf_l[(size_t)MROWS * DDIM];
__device__ __nv_bfloat16 g_qp_h[(size_t)MROWS * DDIM],  g_qp_l[(size_t)MROWS * DDIM];
__device__ __nv_bfloat16 g_kp_h[(size_t)MROWS * DDIM],  g_kp_l[(size_t)MROWS * DDIM];
__device__ __nv_bfloat16 g_vt_h[(size_t)MROWS * DDIM],  g_vt_l[(size_t)MROWS * DDIM];
__device__ __nv_bfloat16 g_ao_h[(size_t)MROWS * DDIM];
__device__ __nv_bfloat16 g_hh[(size_t)MROWS * FFD],     g_hl[(size_t)MROWS * FFD];
__device__ __nv_bfloat16 g_w_h[(size_t)12 * 1024 * 1024], g_w_l[(size_t)12 * 1024 * 1024];
__device__ __nv_bfloat16 g_attn_h[(size_t)BB * NH * QQL * KKL];   // 256 MB
__device__ float g_v[(size_t)MROWS * DDIM];
__device__ float g_scores[(size_t)BB * NH * QQL * KKL];           // 512 MB
__device__ float g_x[(size_t)MROWS * DDIM];
__device__ int   g_mask_flag;

// ---------------- cp.async helpers ----------------
__device__ __forceinline__ void cpa16(uint32_t dst, const void* src) {
    asm volatile("cp.async.cg.shared.global [%0], [%1], 16;\n" :: "r"(dst), "l"(src));
}
__device__ __forceinline__ void cpa_commit() { asm volatile("cp.async.commit_group;\n"); }
__device__ __forceinline__ void cpa_wait0() { asm volatile("cp.async.wait_group 0;\n"); }
__device__ __forceinline__ void cpa_wait1() { asm volatile("cp.async.wait_group 1;\n"); }

// ---------------- mask dtype sniffing ----------------
__global__ void detect_mask_kernel(const unsigned char* __restrict__ m) {
    __shared__ int c1, c2, c3;
    if (threadIdx.x == 0) { c1 = 0; c2 = 0; c3 = 0; }
    __syncthreads();
    for (int i = threadIdx.x; i < BB * KKL; i += blockDim.x) {
        unsigned char v = m[i];
        if (v) {
            int p = i & 3;
            if (p == 1) atomicAdd(&c1, 1);
            else if (p == 2) atomicAdd(&c2, 1);
            else if (p == 3) atomicAdd(&c3, 1);
        }
    }
    __syncthreads();
    if (threadIdx.x == 0) {
        int f;
        if (c1 == 0 && c2 == 0 && c3 == 0) f = 0;  // int32
        else if (c1 == 0) f = 2;                   // float32
        else f = 1;                                // uint8
        g_mask_flag = f;
    }
}

__device__ __forceinline__ bool mask_valid(const void* m, int idx, int flag) {
    if (flag == 1) return ((const unsigned char*)m)[idx] != 0;
    if (flag == 2) return ((const float*)m)[idx] != 0.0f;
    return ((const int*)m)[idx] != 0;
}

// ---------------- split fp32 -> bf16 hi/lo ----------------
__global__ void __launch_bounds__(256) split_kernel(
    const float* __restrict__ x, __nv_bfloat16* __restrict__ hi,
    __nv_bfloat16* __restrict__ lo, size_t n)
{
    size_t i = ((size_t)blockIdx.x * 256 + threadIdx.x) * 4;
    if (i >= n) return;
    float4 v = *(const float4*)(x + i);
    __nv_bfloat16 h0 = __float2bfloat16_rn(v.x);
    __nv_bfloat16 h1 = __float2bfloat16_rn(v.y);
    __nv_bfloat16 h2 = __float2bfloat16_rn(v.z);
    __nv_bfloat16 h3 = __float2bfloat16_rn(v.w);
    __nv_bfloat162* hp = (__nv_bfloat162*)(hi + i);
    hp[0] = __nv_bfloat162(h0, h1);
    hp[1] = __nv_bfloat162(h2, h3);
    __nv_bfloat162* lp = (__nv_bfloat162*)(lo + i);
    lp[0] = __nv_bfloat162(__float2bfloat16_rn(v.x - __bfloat162float(h0)),
                           __float2bfloat16_rn(v.y - __bfloat162float(h1)));
    lp[1] = __nv_bfloat162(__float2bfloat16_rn(v.z - __bfloat162float(h2)),
                           __float2bfloat16_rn(v.w - __bfloat162float(h3)));
}

// ---------------- layernorm -> split bf16 hi/lo ----------------
__global__ void __launch_bounds__(256) ln_split_kernel(
    const float* __restrict__ x, const float* __restrict__ w,
    const float* __restrict__ b, __nv_bfloat16* __restrict__ hi,
    __nv_bfloat16* __restrict__ lo)
{
    int row = blockIdx.x;
    const float* xr = x + (size_t)row * DDIM;
    float sum = 0.f, sumsq = 0.f;
    for (int i = threadIdx.x; i < DDIM; i += blockDim.x) {
        float v = xr[i]; sum += v; sumsq += v * v;
    }
    __shared__ float s1[32], s2[32];
    for (int o = 16; o; o >>= 1) {
        sum   += __shfl_down_sync(0xffffffffu, sum, o);
        sumsq += __shfl_down_sync(0xffffffffu, sumsq, o);
    }
    int lane = threadIdx.x & 31, wid = threadIdx.x >> 5;
    if (lane == 0) { s1[wid] = sum; s2[wid] = sumsq; }
    __syncthreads();
    if (wid == 0) {
        sum   = lane < 8 ? s1[lane] : 0.f;
        sumsq = lane < 8 ? s2[lane] : 0.f;
        for (int o = 4; o; o >>= 1) {
            sum   += __shfl_down_sync(0xffffffffu, sum, o);
            sumsq += __shfl_down_sync(0xffffffffu, sumsq, o);
        }
        if (lane == 0) { s1[0] = sum; s2[0] = sumsq; }
    }
    __syncthreads();
    float mu  = s1[0] * (1.0f / DDIM);
    float var = s2[0] * (1.0f / DDIM) - mu * mu;
    float inv = rsqrtf(var + 1e-5f);
    size_t base = (size_t)row * DDIM;
    for (int i = threadIdx.x; i < DDIM; i += blockDim.x) {
        float v = (xr[i] - mu) * inv * w[i] + b[i];
        __nv_bfloat16 h = __float2bfloat16_rn(v);
        hi[base + i] = h;
        lo[base + i] = __float2bfloat16_rn(v - __bfloat162float(h));
    }
}

// ---------------- tensor-core GEMM building blocks ----------------
__device__ __forceinline__ float gelu_exact(float v) {
    return 0.5f * v * (1.0f + erff(v * 0.70710678118654752f));
}

__device__ __forceinline__ void mma_bf16(float* c, const uint32_t* a, uint32_t b0, uint32_t b1) {
    asm volatile(
        "mma.sync.aligned.m16n8k16.row.col.f32.bf16.bf16.f32 "
        "{%0,%1,%2,%3}, {%4,%5,%6,%7}, {%8,%9}, {%0,%1,%2,%3};\n"
        : "+f"(c[0]), "+f"(c[1]), "+f"(c[2]), "+f"(c[3])
        : "r"(a[0]), "r"(a[1]), "r"(a[2]), "r"(a[3]), "r"(b0), "r"(b1));
}

__device__ __forceinline__ void ldsm_x4(uint32_t* r, uint32_t addr) {
    asm volatile("ldmatrix.sync.aligned.m8n8.x4.shared.b16 {%0,%1,%2,%3}, [%4];\n"
                 : "=r"(r[0]), "=r"(r[1]), "=r"(r[2]), "=r"(r[3]) : "r"(addr));
}

// ---------------- unified split-bf16 GEMM (1-pass or 3-pass), optional batch ----------------
// C[M,N] = A[M,K]*W[N,K]^T ; cp.async 2-stage ping-pong, dynamic smem.
// block 128x128, BK=32, 256 threads, warps 2(m)x4(n), warp tile 64x32.
__global__ void __launch_bounds__(256, 2) gemm3_kernel(
    const __nv_bfloat16* __restrict__ Ah, const __nv_bfloat16* __restrict__ Al,
    long lda, long sAb, long sAhh,
    const __nv_bfloat16* __restrict__ Wh, const __nv_bfloat16* __restrict__ Wl,
    long ldb, long sBb, long sBhh,
    const float* __restrict__ bias, const float* __restrict__ resid,
    float* __restrict__ Cf, __nv_bfloat16* __restrict__ Ch, __nv_bfloat16* __restrict__ Cl,
    long ldc, long sCb, long sChh,
    int Kd, float scale, int act, int three)
{
    extern __shared__ __nv_bfloat16 sm[];
    const int SP = three ? 4 * PLANE : 2 * PLANE;   // stage stride (elems)
    const int tid = threadIdx.x;
    const int lane = tid & 31;
    const int warp = tid >> 5;
    const int wm = warp >> 2, wn = warp & 3;
    const int zb = blockIdx.z / NH, zh = blockIdx.z % NH;
    const size_t Aoff = (size_t)zb * sAb + (size_t)zh * sAhh;
    const size_t Boff = (size_t)zb * sBb + (size_t)zh * sBhh;
    const size_t Coff = (size_t)zb * sCb + (size_t)zh * sChh;
    const size_t bm = (size_t)blockIdx.y * 128, bn = (size_t)blockIdx.x * 128;

    const int lrow = tid >> 1;
    const int lseg = (tid & 1) * 16;
    const __nv_bfloat16* gAh = Ah + Aoff + (bm + lrow) * (size_t)lda + lseg;
    const __nv_bfloat16* gAl = Al + Aoff + (bm + lrow) * (size_t)lda + lseg;
    const __nv_bfloat16* gBh = Wh + Boff + (bn + lrow) * (size_t)ldb + lseg;
    const __nv_bfloat16* gBl = Wl + Boff + (bn + lrow) * (size_t)ldb + lseg;
    const int soff = lrow * GS + lseg;

    const uint32_t smBase = (uint32_t)__cvta_generic_to_shared(sm);
    const int arow = wm * 64 + (lane & 15);
    const int acol = (lane >> 4) << 3;
    const int bg = lane >> 2;
    const int bt = (lane & 3) << 1;

    float acc[4][4][4];
#pragma unroll
    for (int i = 0; i < 4; i++)
#pragma unroll
        for (int j = 0; j < 4; j++)
#pragma unroll
            for (int t = 0; t < 4; t++) acc[i][j][t] = 0.f;

    const int ntiles = Kd >> 5;

    // stage loader
    auto load_stage = [&](int st, int k0) {
        uint32_t d = smBase + (uint32_t)(st * SP + soff) * 2;
        cpa16(d,                  gAh + k0);
        cpa16(d + 16,             gAh + k0 + 8);
        cpa16(d + PLANE * 2,      gBh + k0);
        cpa16(d + PLANE * 2 + 16, gBh + k0 + 8);
        if (three) {
            cpa16(d + 2 * PLANE * 2,      gAl + k0);
            cpa16(d + 2 * PLANE * 2 + 16, gAl + k0 + 8);
            cpa16(d + 3 * PLANE * 2,      gBl + k0);
            cpa16(d + 3 * PLANE * 2 + 16, gBl + k0 + 8);
        }
    };

    load_stage(0, 0);
    cpa_commit();

    for (int it = 0; it < ntiles; it++) {
        if (it + 1 < ntiles) { load_stage((it + 1) & 1, (it + 1) << 5); cpa_commit(); cpa_wait1(); }
        else cpa_wait0();
        __syncthreads();

        const int st = it & 1;
        const uint32_t aH = smBase + (uint32_t)(st * SP) * 2;
        const uint32_t aL = aH + 2 * PLANE * 2;
        const __nv_bfloat16* sBh = sm + st * SP + PLANE;
        const __nv_bfloat16* sBl = sm + st * SP + 3 * PLANE;

#pragma unroll
        for (int ks = 0; ks < 32; ks += 16) {
            uint32_t afh[4][4], afl[4][4];
#pragma unroll
            for (int mi = 0; mi < 4; mi++) {
                uint32_t off = (uint32_t)(((arow + mi * 16) * GS + ks + acol) * 2);
                ldsm_x4(afh[mi], aH + off);
                if (three) ldsm_x4(afl[mi], aL + off);
            }
#pragma unroll
            for (int ni = 0; ni < 4; ni++) {
                int bidx = (wn * 32 + ni * 8 + bg) * GS + ks + bt;
                uint32_t bh0 = *(const uint32_t*)&sBh[bidx];
                uint32_t bh1 = *(const uint32_t*)&sBh[bidx + 8];
#pragma unroll
                for (int mi = 0; mi < 4; mi++)
                    mma_bf16(acc[mi][ni], afh[mi], bh0, bh1);
                if (three) {
                    uint32_t bl0 = *(const uint32_t*)&sBl[bidx];
                    uint32_t bl1 = *(const uint32_t*)&sBl[bidx + 8];
#pragma unroll
                    for (int mi = 0; mi < 4; mi++) {
                        mma_bf16(acc[mi][ni], afl[mi], bh0, bh1);
                        mma_bf16(acc[mi][ni], afh[mi], bl0, bl1);
                    }
                }
            }
        }
        __syncthreads();
    }

    const int gr = lane >> 2;
    const int gc = (lane & 3) << 1;
#pragma unroll
    for (int mi = 0; mi < 4; mi++) {
        size_t r0 = bm + wm * 64 + mi * 16 + gr;
#pragma unroll
        for (int ni = 0; ni < 4; ni++) {
            size_t c0 = bn + wn * 32 + ni * 8 + gc;
            float bv0 = bias ? bias[c0] : 0.f;
            float bv1 = bias ? bias[c0 + 1] : 0.f;
#pragma unroll
            for (int half = 0; half < 2; half++) {
                size_t row = r0 + half * 8;
                float v0 = acc[mi][ni][half * 2 + 0] * scale + bv0;
                float v1 = acc[mi][ni][half * 2 + 1] * scale + bv1;
                size_t o = Coff + row * ldc + c0;
                if (resid) {
                    float2 rv = *(const float2*)(resid + o);
                    v0 += rv.x; v1 += rv.y;
                }
                if (act) { v0 = gelu_exact(v0); v1 = gelu_exact(v1); }
                if (Cf) *(float2*)(Cf + o) = make_float2(v0, v1);
                if (Ch) {
                    __nv_bfloat16 h0 = __float2bfloat16_rn(v0);
                    __nv_bfloat16 h1 = __float2bfloat16_rn(v1);
                    *(__nv_bfloat162*)(Ch + o) = __nv_bfloat162(h0, h1);
                    *(__nv_bfloat162*)(Cl + o) = __nv_bfloat162(
                        __float2bfloat16_rn(v0 - __bfloat162float(h0)),
                        __float2bfloat16_rn(v1 - __bfloat162float(h1)));
                }
            }
        }
    }
}

// ---------------- transpose + split V: vt[b, c, k] = v[b*1024+k, c] ----------------
__global__ void __launch_bounds__(256) transpose_split_kernel(
    const float* __restrict__ v, __nv_bfloat16* __restrict__ th, __nv_bfloat16* __restrict__ tl)
{
    __shared__ float tile[32][33];
    int tx = threadIdx.x, ty = threadIdx.y;
    int c0 = blockIdx.x * 32;
    int r0 = blockIdx.y * 32;
#pragma unroll
    for (int i = 0; i < 4; i++)
        tile[ty + i * 8][tx] = v[(size_t)(r0 + ty + i * 8) * DDIM + c0 + tx];
    __syncthreads();
    int b = r0 >> 10;
    int kk0 = r0 & 1023;
#pragma unroll
    for (int i = 0; i < 4; i++) {
        float val = tile[tx][ty + i * 8];
        size_t o = ((size_t)(b << 10) + c0 + ty + i * 8) * 1024 + kk0 + tx;
        __nv_bfloat16 h = __float2bfloat16_rn(val);
        th[o] = h;
        tl[o] = __float2bfloat16_rn(val - __bfloat162float(h));
    }
}

// ---------------- fused masked softmax + head mean ----------------
// block per (b,q): 16 heads x 1024 keys. Thread t owns keys [4t, 4t+4).
__global__ void __launch_bounds__(256) softmax_mean_kernel(
    const float* __restrict__ S, const void* __restrict__ mask,
    __nv_bfloat16* __restrict__ ah, float* __restrict__ mout)
{
    const int bq = blockIdx.x;
    const int b = bq >> 10, q = bq & 1023;
    const int t = threadIdx.x;
    const int k0 = t * 4;
    const int flag = g_mask_flag;
    const int lane = t & 31, w = t >> 5;

    bool mk[4];
#pragma unroll
    for (int i = 0; i < 4; i++) mk[i] = mask_valid(mask, b * KKL + k0 + i, flag);

    float macc[4] = {0.f, 0.f, 0.f, 0.f};
    __shared__ float red[8];

    for (int h = 0; h < NH; h++) {
        const float* r = S + (((size_t)(b * NH + h)) * QQL + q) * KKL;
        float4 v4 = *(const float4*)(r + k0);
        float vals[4] = {v4.x, v4.y, v4.z, v4.w};
        const float NEG = -__int_as_float(0x7f800000);
#pragma unroll
        for (int i = 0; i < 4; i++) if (!mk[i]) vals[i] = NEG;

        // block max
        float mx = fmaxf(fmaxf(vals[0], vals[1]), fmaxf(vals[2], vals[3]));
#pragma unroll
        for (int o = 16; o; o >>= 1) mx = fmaxf(mx, __shfl_xor_sync(0xffffffffu, mx, o));
        if (lane == 0) red[w] = mx;
        __syncthreads();
        mx = red[0];
#pragma unroll
        for (int j = 1; j < 8; j++) mx = fmaxf(mx, red[j]);
        __syncthreads();

        // exp + block sum
        float sum = 0.f;
#pragma unroll
        for (int i = 0; i < 4; i++) { vals[i] = expf(vals[i] - mx); sum += vals[i]; }
#pragma unroll
        for (int o = 16; o; o >>= 1) sum += __shfl_xor_sync(0xffffffffu, sum, o);
        if (lane == 0) red[w] = sum;
        __syncthreads();
        float tot = red[0];
#pragma unroll
        for (int j = 1; j < 8; j++) tot += red[j];
        __syncthreads();
        float inv = 1.0f / tot;

        // probs: bf16 store + fp32 mean accumulation
        __nv_bfloat162 p01, p23;
        float p0 = vals[0] * inv, p1 = vals[1] * inv, p2 = vals[2] * inv, p3 = vals[3] * inv;
        macc[0] += p0; macc[1] += p1; macc[2] += p2; macc[3] += p3;
        p01 = __nv_bfloat162(__float2bfloat16_rn(p0), __float2bfloat16_rn(p1));
        p23 = __nv_bfloat162(__float2bfloat16_rn(p2), __float2bfloat16_rn(p3));
        __nv_bfloat162* dst = (__nv_bfloat162*)(ah + (((size_t)(b * NH + h)) * QQL + q) * KKL + k0);
        dst[0] = p01; dst[1] = p23;
    }

    float4 mo;
    mo.x = macc[0] * (1.0f / NH); mo.y = macc[1] * (1.0f / NH);
    mo.z = macc[2] * (1.0f / NH); mo.w = macc[3] * (1.0f / NH);
    *(float4*)(mout + ((size_t)bq) * KKL + k0) = mo;
}

// ---------------- AV: ao[b,q,h*64+n] = sum_k attn_h[b,h,q,k] * vt[b,h*64+n,k] ----------------
// 1-pass bf16, cp.async 2-stage. block 128(m) x 64(n), warps 2(m)x4(n): warp tile 64x16
#define AVP (128*GS)      /* A plane elems */
#define BVP (64*GS)       /* B plane elems */
__global__ void __launch_bounds__(256, 2) av_kernel(
    const __nv_bfloat16* __restrict__ attn, const __nv_bfloat16* __restrict__ vt,
    __nv_bfloat16* __restrict__ Ch)
{
    __shared__ __nv_bfloat16 sm[2 * (AVP + BVP)];
    const int tid = threadIdx.x;
    const int lane = tid & 31;
    const int warp = tid >> 5;
    const int wm = warp >> 2, wn = warp & 3;
    const int z = blockIdx.z;
    const int b = z / NH, h = z % NH;
    const size_t bm = (size_t)blockIdx.y * 128;

    const __nv_bfloat16* A = attn + (size_t)z * QQL * KKL;
    const __nv_bfloat16* W = vt + ((size_t)b * 1024 + h * 64) * 1024;
    const size_t Coff = (size_t)b * QQL * DDIM + h * HDIM;

    const int lrow = tid >> 1;
    const int lseg = (tid & 1) * 16;
    const __nv_bfloat16* gA = A + (bm + lrow) * (size_t)KKL + lseg;
    const int soffA = lrow * GS + lseg;
    const int brow = tid >> 2;
    const int bseg = (tid & 3) * 8;
    const __nv_bfloat16* gB = W + (size_t)brow * 1024 + bseg;
    const int soffB = brow * GS + bseg;

    const uint32_t smBase = (uint32_t)__cvta_generic_to_shared(sm);
    const int arow = wm * 64 + (lane & 15);
    const int acol = (lane >> 4) << 3;
    const int bg = lane >> 2;
    const int bt = (lane & 3) << 1;
    const int SP2 = AVP + BVP;

    float acc[4][2][4];
#pragma unroll
    for (int i = 0; i < 4; i++)
#pragma unroll
        for (int j = 0; j < 2; j++)
#pragma unroll
            for (int t = 0; t < 4; t++) acc[i][j][t] = 0.f;

    auto load_stage = [&](int st, int k0) {
        uint32_t d = smBase + (uint32_t)(st * SP2 + soffA) * 2;
        cpa16(d,      gA + k0);
        cpa16(d + 16, gA + k0 + 8);
        uint32_t db = smBase + (uint32_t)(st * SP2 + AVP + soffB) * 2;
        cpa16(db, gB + k0);
    };

    load_stage(0, 0);
    cpa_commit();

    for (int it = 0; it < 32; it++) {
        if (it + 1 < 32) { load_stage((it + 1) & 1, (it + 1) << 5); cpa_commit(); cpa_wait1(); }
        else cpa_wait0();
        __syncthreads();

        const int st = it & 1;
        const uint32_t aBase = smBase + (uint32_t)(st * SP2) * 2;
        const __nv_bfloat16* sB = sm + st * SP2 + AVP;

#pragma unroll
        for (int ks = 0; ks < 32; ks += 16) {
            uint32_t af[4][4];
#pragma unroll
            for (int mi = 0; mi < 4; mi++) {
                uint32_t off = (uint32_t)(((arow + mi * 16) * GS + ks + acol) * 2);
                ldsm_x4(af[mi], aBase + off);
            }
#pragma unroll
            for (int ni = 0; ni < 2; ni++) {
                int bidx = (wn * 16 + ni * 8 + bg) * GS + ks + bt;
                uint32_t b0 = *(const uint32_t*)&sB[bidx];
                uint32_t b1 = *(const uint32_t*)&sB[bidx + 8];
#pragma unroll
                for (int mi = 0; mi < 4; mi++)
                    mma_bf16(acc[mi][ni], af[mi], b0, b1);
            }
        }
        __syncthreads();
    }

    const int gr = lane >> 2;
    const int gc = (lane & 3) << 1;
#pragma unroll
    for (int mi = 0; mi < 4; mi++) {
        size_t r0 = bm + wm * 64 + mi * 16 + gr;
#pragma unroll
        for (int ni = 0; ni < 2; ni++) {
            int c0 = wn * 16 + ni * 8 + gc;
#pragma unroll
            for (int half = 0; half < 2; half++) {
                size_t row = r0 + half * 8;
                size_t o = Coff + row * DDIM + c0;
                *(__nv_bfloat162*)(Ch + o) = __nv_bfloat162(
                    __float2bfloat16_rn(acc[mi][ni][half * 2 + 0]),
                    __float2bfloat16_rn(acc[mi][ni][half * 2 + 1]));
            }
        }
    }
}

// ---------------- launch ----------------
extern "C" void kernel_launch(void* const* d_in, const int* in_sizes, int n_in,
                              void* d_out, int out_size)
{
    const float* query      = (const float*)d_in[0];
    const float* key_value  = (const float*)d_in[1];
    const void*  kpm        = d_in[2];
    const float* ln_q_w     = (const float*)d_in[3];
    const float* ln_q_b     = (const float*)d_in[4];
    const float* ln_kv_w    = (const float*)d_in[5];
    const float* ln_kv_b    = (const float*)d_in[6];
    const float* ln_f_w     = (const float*)d_in[7];
    const float* ln_f_b     = (const float*)d_in[8];
    const float* in_proj_w  = (const float*)d_in[9];
    const float* in_proj_b  = (const float*)d_in[10];
    const float* out_proj_w = (const float*)d_in[11];
    const float* out_proj_b = (const float*)d_in[12];
    const float* ffn_w1     = (const float*)d_in[13];
    const float* ffn_b1     = (const float*)d_in[14];
    const float* ffn_w2     = (const float*)d_in[15];
    const float* ffn_b2     = (const float*)d_in[16];

    float* out_x    = (float*)d_out;
    float* out_attn = out_x + (size_t)BB * QQL * DDIM;

    __nv_bfloat16 *qnh, *qnl, *kvnh, *kvnl, *lnfh, *lnfl, *aoh, *hh, *hl, *wh, *wl;
    __nv_bfloat16 *qph, *qpl, *kph, *kpl, *vth, *vtl, *ath;
    float *vp, *sc, *xb;
    cudaGetSymbolAddress((void**)&qnh,  g_qn_h);  cudaGetSymbolAddress((void**)&qnl,  g_qn_l);
    cudaGetSymbolAddress((void**)&kvnh, g_kvn_h); cudaGetSymbolAddress((void**)&kvnl, g_kvn_l);
    cudaGetSymbolAddress((void**)&lnfh, g_lnf_h); cudaGetSymbolAddress((void**)&lnfl, g_lnf_l);
    cudaGetSymbolAddress((void**)&aoh,  g_ao_h);
    cudaGetSymbolAddress((void**)&hh,   g_hh);    cudaGetSymbolAddress((void**)&hl,   g_hl);
    cudaGetSymbolAddress((void**)&wh,   g_w_h);   cudaGetSymbolAddress((void**)&wl,   g_w_l);
    cudaGetSymbolAddress((void**)&qph,  g_qp_h);  cudaGetSymbolAddress((void**)&qpl,  g_qp_l);
    cudaGetSymbolAddress((void**)&kph,  g_kp_h);  cudaGetSymbolAddress((void**)&kpl,  g_kp_l);
    cudaGetSymbolAddress((void**)&vth,  g_vt_h);  cudaGetSymbolAddress((void**)&vtl,  g_vt_l);
    cudaGetSymbolAddress((void**)&ath,  g_attn_h);
    cudaGetSymbolAddress((void**)&vp,   g_v);
    cudaGetSymbolAddress((void**)&sc,   g_scores);
    cudaGetSymbolAddress((void**)&xb,   g_x);

    const size_t M1 = (size_t)1024 * 1024;
    const size_t OFF_OUT  = 3 * M1;
    const size_t OFF_FFN1 = 4 * M1;
    const size_t OFF_FFN2 = 8 * M1;

    static int attr_done = 0;
    if (!attr_done) {
        cudaFuncSetAttribute(gemm3_kernel, cudaFuncAttributeMaxDynamicSharedMemorySize, 8 * PLANE * 2);
        attr_done = 1;
    }
    const int SM3 = 8 * PLANE * 2;   // 3-pass: 4 planes x 2 stages x 2B
    const int SM1 = 4 * PLANE * 2;   // 1-pass: 2 planes x 2 stages x 2B

    detect_mask_kernel<<<1, 256>>>((const unsigned char*)kpm);

    split_kernel<<<(unsigned)(3 * M1 / 1024), 256>>>(in_proj_w,  wh,            wl,            3 * M1);
    split_kernel<<<(unsigned)(1 * M1 / 1024), 256>>>(out_proj_w, wh + OFF_OUT,  wl + OFF_OUT,  1 * M1);
    split_kernel<<<(unsigned)(4 * M1 / 1024), 256>>>(ffn_w1,     wh + OFF_FFN1, wl + OFF_FFN1, 4 * M1);
    split_kernel<<<(unsigned)(4 * M1 / 1024), 256>>>(ffn_w2,     wh + OFF_FFN2, wl + OFF_FFN2, 4 * M1);

    ln_split_kernel<<<MROWS, 256>>>(query,     ln_q_w,  ln_q_b,  qnh,  qnl);
    ln_split_kernel<<<MROWS, 256>>>(key_value, ln_kv_w, ln_kv_b, kvnh, kvnl);

    dim3 g1024(DDIM / 128, MROWS / 128, 1);
    // q proj (3-pass, bf16 hi/lo out)
    gemm3_kernel<<<g1024, 256, SM3>>>(qnh, qnl, DDIM, 0, 0, wh, wl, DDIM, 0, 0,
                                 in_proj_b, nullptr, nullptr, qph, qpl, DDIM, 0, 0,
                                 DDIM, 1.f, 0, 1);
    // k proj (3-pass, bf16 hi/lo out)
    gemm3_kernel<<<g1024, 256, SM3>>>(kvnh, kvnl, DDIM, 0, 0, wh + M1, wl + M1, DDIM, 0, 0,
                                 in_proj_b + DDIM, nullptr, nullptr, kph, kpl, DDIM, 0, 0,
                                 DDIM, 1.f, 0, 1);
    // v proj (1-pass, fp32 out)
    gemm3_kernel<<<g1024, 256, SM1>>>(kvnh, kvnh, DDIM, 0, 0, wh + 2 * M1, wh + 2 * M1, DDIM, 0, 0,
                                 in_proj_b + 2 * DDIM, nullptr, vp, nullptr, nullptr, DDIM, 0, 0,
                                 DDIM, 1.f, 0, 0);
    transpose_split_kernel<<<dim3(DDIM / 32, MROWS / 32), dim3(32, 8)>>>(vp, vth, vtl);

    // scores (3-pass batched, Kd=64, scale fused)
    dim3 gsc(KKL / 128, QQL / 128, BB * NH);
    gemm3_kernel<<<gsc, 256, SM3>>>(qph, qpl, DDIM, (long)QQL * DDIM, HDIM,
                               kph, kpl, DDIM, (long)KKL * DDIM, HDIM,
                               nullptr, nullptr, sc, nullptr, nullptr,
                               KKL, (long)NH * QQL * KKL, (long)QQL * KKL,
                               HDIM, 0.125f, 0, 1);

    // fused softmax + head-mean
    softmax_mean_kernel<<<BB * QQL, 256>>>(sc, kpm, ath, out_attn);

    dim3 gav(1, QQL / 128, BB * NH);
    av_kernel<<<gav, 256>>>(ath, vth, aoh);

    // out_proj + residual (1-pass)
    gemm3_kernel<<<g1024, 256, SM1>>>(aoh, aoh, DDIM, 0, 0, wh + OFF_OUT, wh + OFF_OUT, DDIM, 0, 0,
                                 out_proj_b, query, xb, nullptr, nullptr, DDIM, 0, 0,
                                 DDIM, 1.f, 0, 0);

    ln_split_kernel<<<MROWS, 256>>>(xb, ln_f_w, ln_f_b, lnfh, lnfl);

    // ffn1 (3-pass, gelu, bf16 hi/lo out)
    dim3 gff1(FFD / 128, MROWS / 128, 1);
    gemm3_kernel<<<gff1, 256, SM3>>>(lnfh, lnfl, DDIM, 0, 0, wh + OFF_FFN1, wl + OFF_FFN1, DDIM, 0, 0,
                                ffn_b1, nullptr, nullptr, hh, hl, FFD, 0, 0,
                                DDIM, 1.f, 1, 1);
    // ffn2 (3-pass, residual, fp32 out)
    gemm3_kernel<<<g1024, 256, SM3>>>(hh, hl, FFD, 0, 0, wh + OFF_FFN2, wl + OFF_FFN2, FFD, 0, 0,
                                 ffn_b2, xb, out_x, nullptr, nullptr, DDIM, 0, 0,
                                 FFD, 1.f, 0, 1);
}

// round 9
// speedup vs baseline: 2.9982x; 1.0420x over previous
#include <cuda_runtime.h>
#include <cuda_bf16.h>
#include <math.h>
#include <stdint.h>

#define BB 8
#define QQL 1024
#define KKL 1024
#define DDIM 1024
#define NH 16
#define HDIM 64
#define FFD 4096
#define MROWS (BB*QQL)   /* 8192 */
#define GS 40            /* smem row stride (bf16 elems); 80B rows, 16B-aligned segs */
#define APLANE (256*GS)  /* A plane elems (256 rows) */
#define BPLANE (128*GS)  /* B plane elems (128 rows) */

// ---------------- scratch (device globals) ----------------
__device__ __nv_bfloat16 g_qn_h[(size_t)MROWS * DDIM],  g_qn_l[(size_t)MROWS * DDIM];
__device__ __nv_bfloat16 g_kvn_h[(size_t)MROWS * DDIM], g_kvn_l[(size_t)MROWS * DDIM];
__device__ __nv_bfloat16 g_lnf_h[(size_t)MROWS * DDIM], g_lnf_l[(size_t)MROWS * DDIM];
__device__ __nv_bfloat16 g_qp_h[(size_t)MROWS * DDIM],  g_qp_l[(size_t)MROWS * DDIM];
__device__ __nv_bfloat16 g_kp_h[(size_t)MROWS * DDIM],  g_kp_l[(size_t)MROWS * DDIM];
__device__ __nv_bfloat16 g_vt_h[(size_t)MROWS * DDIM];
__device__ __nv_bfloat16 g_ao_h[(size_t)MROWS * DDIM];
__device__ __nv_bfloat16 g_hh[(size_t)MROWS * FFD],     g_hl[(size_t)MROWS * FFD];
__device__ __nv_bfloat16 g_w_h[(size_t)12 * 1024 * 1024], g_w_l[(size_t)12 * 1024 * 1024];
__device__ __nv_bfloat16 g_attn_h[(size_t)BB * NH * QQL * KKL];   // 256 MB
__device__ float g_v[(size_t)MROWS * DDIM];
__device__ float g_scores[(size_t)BB * NH * QQL * KKL];           // 512 MB
__device__ float g_x[(size_t)MROWS * DDIM];
__device__ int   g_mask_flag;

// ---------------- helpers ----------------
__device__ __forceinline__ uint32_t smem_u32(const void* p) {
    return (uint32_t)__cvta_generic_to_shared(p);
}
__device__ __forceinline__ void cpa16(uint32_t dst, const void* src) {
    asm volatile("cp.async.cg.shared.global [%0], [%1], 16;\n" :: "r"(dst), "l"(src));
}
__device__ __forceinline__ void cpa_commit() { asm volatile("cp.async.commit_group;\n"); }
__device__ __forceinline__ void cpa_wait0() { asm volatile("cp.async.wait_group 0;\n"); }
__device__ __forceinline__ void cpa_wait1() { asm volatile("cp.async.wait_group 1;\n"); }

__device__ __forceinline__ void mma_bf16(float* c, const uint32_t* a, uint32_t b0, uint32_t b1) {
    asm volatile(
        "mma.sync.aligned.m16n8k16.row.col.f32.bf16.bf16.f32 "
        "{%0,%1,%2,%3}, {%4,%5,%6,%7}, {%8,%9}, {%0,%1,%2,%3};\n"
        : "+f"(c[0]), "+f"(c[1]), "+f"(c[2]), "+f"(c[3])
        : "r"(a[0]), "r"(a[1]), "r"(a[2]), "r"(a[3]), "r"(b0), "r"(b1));
}
__device__ __forceinline__ void ldsm_x4(uint32_t* r, uint32_t addr) {
    asm volatile("ldmatrix.sync.aligned.m8n8.x4.shared.b16 {%0,%1,%2,%3}, [%4];\n"
                 : "=r"(r[0]), "=r"(r[1]), "=r"(r[2]), "=r"(r[3]) : "r"(addr));
}
__device__ __forceinline__ float gelu_exact(float v) {
    return 0.5f * v * (1.0f + erff(v * 0.70710678118654752f));
}

// ---------------- mask dtype sniffing ----------------
__global__ void detect_mask_kernel(const unsigned char* __restrict__ m) {
    __shared__ int c1, c2, c3;
    if (threadIdx.x == 0) { c1 = 0; c2 = 0; c3 = 0; }
    __syncthreads();
    for (int i = threadIdx.x; i < BB * KKL; i += blockDim.x) {
        unsigned char v = m[i];
        if (v) {
            int p = i & 3;
            if (p == 1) atomicAdd(&c1, 1);
            else if (p == 2) atomicAdd(&c2, 1);
            else if (p == 3) atomicAdd(&c3, 1);
        }
    }
    __syncthreads();
    if (threadIdx.x == 0) {
        int f;
        if (c1 == 0 && c2 == 0 && c3 == 0) f = 0;  // int32
        else if (c1 == 0) f = 2;                   // float32
        else f = 1;                                // uint8
        g_mask_flag = f;
    }
}

__device__ __forceinline__ bool mask_valid(const void* m, int idx, int flag) {
    if (flag == 1) return ((const unsigned char*)m)[idx] != 0;
    if (flag == 2) return ((const float*)m)[idx] != 0.0f;
    return ((const int*)m)[idx] != 0;
}

// ---------------- split fp32 -> bf16 hi/lo ----------------
__global__ void __launch_bounds__(256) split_kernel(
    const float* __restrict__ x, __nv_bfloat16* __restrict__ hi,
    __nv_bfloat16* __restrict__ lo, size_t n)
{
    size_t i = ((size_t)blockIdx.x * 256 + threadIdx.x) * 4;
    if (i >= n) return;
    float4 v = *(const float4*)(x + i);
    __nv_bfloat16 h0 = __float2bfloat16_rn(v.x);
    __nv_bfloat16 h1 = __float2bfloat16_rn(v.y);
    __nv_bfloat16 h2 = __float2bfloat16_rn(v.z);
    __nv_bfloat16 h3 = __float2bfloat16_rn(v.w);
    __nv_bfloat162* hp = (__nv_bfloat162*)(hi + i);
    hp[0] = __nv_bfloat162(h0, h1);
    hp[1] = __nv_bfloat162(h2, h3);
    __nv_bfloat162* lp = (__nv_bfloat162*)(lo + i);
    lp[0] = __nv_bfloat162(__float2bfloat16_rn(v.x - __bfloat162float(h0)),
                           __float2bfloat16_rn(v.y - __bfloat162float(h1)));
    lp[1] = __nv_bfloat162(__float2bfloat16_rn(v.z - __bfloat162float(h2)),
                           __float2bfloat16_rn(v.w - __bfloat162float(h3)));
}

// ---------------- layernorm -> split bf16 hi/lo ----------------
__global__ void __launch_bounds__(256) ln_split_kernel(
    const float* __restrict__ x, const float* __restrict__ w,
    const float* __restrict__ b, __nv_bfloat16* __restrict__ hi,
    __nv_bfloat16* __restrict__ lo)
{
    int row = blockIdx.x;
    const float* xr = x + (size_t)row * DDIM;
    float sum = 0.f, sumsq = 0.f;
    for (int i = threadIdx.x; i < DDIM; i += blockDim.x) {
        float v = xr[i]; sum += v; sumsq += v * v;
    }
    __shared__ float s1[32], s2[32];
    for (int o = 16; o; o >>= 1) {
        sum   += __shfl_down_sync(0xffffffffu, sum, o);
        sumsq += __shfl_down_sync(0xffffffffu, sumsq, o);
    }
    int lane = threadIdx.x & 31, wid = threadIdx.x >> 5;
    if (lane == 0) { s1[wid] = sum; s2[wid] = sumsq; }
    __syncthreads();
    if (wid == 0) {
        sum   = lane < 8 ? s1[lane] : 0.f;
        sumsq = lane < 8 ? s2[lane] : 0.f;
        for (int o = 4; o; o >>= 1) {
            sum   += __shfl_down_sync(0xffffffffu, sum, o);
            sumsq += __shfl_down_sync(0xffffffffu, sumsq, o);
        }
        if (lane == 0) { s1[0] = sum; s2[0] = sumsq; }
    }
    __syncthreads();
    float mu  = s1[0] * (1.0f / DDIM);
    float var = s2[0] * (1.0f / DDIM) - mu * mu;
    float inv = rsqrtf(var + 1e-5f);
    size_t base = (size_t)row * DDIM;
    for (int i = threadIdx.x; i < DDIM; i += blockDim.x) {
        float v = (xr[i] - mu) * inv * w[i] + b[i];
        __nv_bfloat16 h = __float2bfloat16_rn(v);
        hi[base + i] = h;
        lo[base + i] = __float2bfloat16_rn(v - __bfloat162float(h));
    }
}

// ---------------- split-bf16 GEMM, CTA tile 256x128, 512 threads ----------------
// C[M,N] = A[M,K]*W[N,K]^T ; cp.async 2-stage ping-pong, dynamic smem.
// 16 warps as 4(m)x4(n); warp tile 64x32.
__global__ void __launch_bounds__(512, 1) gemm3_kernel(
    const __nv_bfloat16* __restrict__ Ah, const __nv_bfloat16* __restrict__ Al,
    long lda, long sAb, long sAhh,
    const __nv_bfloat16* __restrict__ Wh, const __nv_bfloat16* __restrict__ Wl,
    long ldb, long sBb, long sBhh,
    const float* __restrict__ bias, const float* __restrict__ resid,
    float* __restrict__ Cf, __nv_bfloat16* __restrict__ Ch, __nv_bfloat16* __restrict__ Cl,
    long ldc, long sCb, long sChh,
    int Kd, float scale, int act, int three)
{
    extern __shared__ __nv_bfloat16 sm[];
    const int SP    = three ? (2 * APLANE + 2 * BPLANE) : (APLANE + BPLANE);
    const int offAl = APLANE;
    const int offBh = three ? 2 * APLANE : APLANE;
    const int offBl = 2 * APLANE + BPLANE;

    const int tid  = threadIdx.x;
    const int lane = tid & 31;
    const int warp = tid >> 5;               // 0..15
    const int wm = warp >> 2, wn = warp & 3; // 4x4
    const int zb = blockIdx.z / NH, zh = blockIdx.z % NH;
    const size_t Aoff = (size_t)zb * sAb + (size_t)zh * sAhh;
    const size_t Boff = (size_t)zb * sBb + (size_t)zh * sBhh;
    const size_t Coff = (size_t)zb * sCb + (size_t)zh * sChh;
    const size_t bm = (size_t)blockIdx.y * 256, bn = (size_t)blockIdx.x * 128;

    // load geometry: 512 threads, 16B chunks. A: 1024 chunks (2/thread), B: 512 (1/thread)
    const int lr   = tid >> 2;               // 0..127
    const int lseg = (tid & 3) * 8;          // elem offset in row
    const __nv_bfloat16* gAh1 = Ah + Aoff + (bm + lr) * (size_t)lda + lseg;
    const __nv_bfloat16* gAh2 = gAh1 + 128 * (size_t)lda;
    const __nv_bfloat16* gAl1 = Al + Aoff + (bm + lr) * (size_t)lda + lseg;
    const __nv_bfloat16* gAl2 = gAl1 + 128 * (size_t)lda;
    const __nv_bfloat16* gBh  = Wh + Boff + (bn + lr) * (size_t)ldb + lseg;
    const __nv_bfloat16* gBl  = Wl + Boff + (bn + lr) * (size_t)ldb + lseg;
    const int soffA1 = lr * GS + lseg;
    const int soffA2 = soffA1 + 128 * GS;
    const int soffB  = lr * GS + lseg;

    const uint32_t smBase = smem_u32(sm);
    const int arow = wm * 64 + (lane & 15);
    const int acol = (lane >> 4) << 3;
    const int bg = lane >> 2;
    const int bt = (lane & 3) << 1;

    float acc[4][4][4];
#pragma unroll
    for (int i = 0; i < 4; i++)
#pragma unroll
        for (int j = 0; j < 4; j++)
#pragma unroll
            for (int t = 0; t < 4; t++) acc[i][j][t] = 0.f;

    const int ntiles = Kd >> 5;

    auto load_stage = [&](int st, int k0) {
        uint32_t base = smBase + (uint32_t)(st * SP) * 2;
        cpa16(base + (uint32_t)soffA1 * 2, gAh1 + k0);
        cpa16(base + (uint32_t)soffA2 * 2, gAh2 + k0);
        cpa16(base + (uint32_t)(offBh + soffB) * 2, gBh + k0);
        if (three) {
            cpa16(base + (uint32_t)(offAl + soffA1) * 2, gAl1 + k0);
            cpa16(base + (uint32_t)(offAl + soffA2) * 2, gAl2 + k0);
            cpa16(base + (uint32_t)(offBl + soffB) * 2, gBl + k0);
        }
    };

    load_stage(0, 0);
    cpa_commit();

    for (int it = 0; it < ntiles; it++) {
        if (it + 1 < ntiles) { load_stage((it + 1) & 1, (it + 1) << 5); cpa_commit(); cpa_wait1(); }
        else cpa_wait0();
        __syncthreads();

        const int st = it & 1;
        const uint32_t aH = smBase + (uint32_t)(st * SP) * 2;
        const uint32_t aL = aH + (uint32_t)offAl * 2;
        const __nv_bfloat16* sBh = sm + st * SP + offBh;
        const __nv_bfloat16* sBl = sm + st * SP + offBl;

#pragma unroll
        for (int ks = 0; ks < 32; ks += 16) {
            uint32_t afh[4][4], afl[4][4];
#pragma unroll
            for (int mi = 0; mi < 4; mi++) {
                uint32_t off = (uint32_t)(((arow + mi * 16) * GS + ks + acol) * 2);
                ldsm_x4(afh[mi], aH + off);
                if (three) ldsm_x4(afl[mi], aL + off);
            }
#pragma unroll
            for (int ni = 0; ni < 4; ni++) {
                int bidx = (wn * 32 + ni * 8 + bg) * GS + ks + bt;
                uint32_t bh0 = *(const uint32_t*)&sBh[bidx];
                uint32_t bh1 = *(const uint32_t*)&sBh[bidx + 8];
#pragma unroll
                for (int mi = 0; mi < 4; mi++)
                    mma_bf16(acc[mi][ni], afh[mi], bh0, bh1);
                if (three) {
                    uint32_t bl0 = *(const uint32_t*)&sBl[bidx];
                    uint32_t bl1 = *(const uint32_t*)&sBl[bidx + 8];
#pragma unroll
                    for (int mi = 0; mi < 4; mi++) {
                        mma_bf16(acc[mi][ni], afl[mi], bh0, bh1);
                        mma_bf16(acc[mi][ni], afh[mi], bl0, bl1);
                    }
                }
            }
        }
        __syncthreads();
    }

    const int gr = lane >> 2;
    const int gc = (lane & 3) << 1;
#pragma unroll
    for (int mi = 0; mi < 4; mi++) {
        size_t r0 = bm + wm * 64 + mi * 16 + gr;
#pragma unroll
        for (int ni = 0; ni < 4; ni++) {
            size_t c0 = bn + wn * 32 + ni * 8 + gc;
            float bv0 = bias ? bias[c0] : 0.f;
            float bv1 = bias ? bias[c0 + 1] : 0.f;
#pragma unroll
            for (int half = 0; half < 2; half++) {
                size_t row = r0 + half * 8;
                float v0 = acc[mi][ni][half * 2 + 0] * scale + bv0;
                float v1 = acc[mi][ni][half * 2 + 1] * scale + bv1;
                size_t o = Coff + row * ldc + c0;
                if (resid) {
                    float2 rv = *(const float2*)(resid + o);
                    v0 += rv.x; v1 += rv.y;
                }
                if (act) { v0 = gelu_exact(v0); v1 = gelu_exact(v1); }
                if (Cf) *(float2*)(Cf + o) = make_float2(v0, v1);
                if (Ch) {
                    __nv_bfloat16 h0 = __float2bfloat16_rn(v0);
                    __nv_bfloat16 h1 = __float2bfloat16_rn(v1);
                    *(__nv_bfloat162*)(Ch + o) = __nv_bfloat162(h0, h1);
                    *(__nv_bfloat162*)(Cl + o) = __nv_bfloat162(
                        __float2bfloat16_rn(v0 - __bfloat162float(h0)),
                        __float2bfloat16_rn(v1 - __bfloat162float(h1)));
                }
            }
        }
    }
}

// ---------------- transpose V (fp32 -> bf16, [b,k,c] -> [b,c,k]) ----------------
__global__ void __launch_bounds__(256) transpose_split_kernel(
    const float* __restrict__ v, __nv_bfloat16* __restrict__ th)
{
    __shared__ float tile[32][33];
    int tx = threadIdx.x, ty = threadIdx.y;
    int c0 = blockIdx.x * 32;
    int r0 = blockIdx.y * 32;
#pragma unroll
    for (int i = 0; i < 4; i++)
        tile[ty + i * 8][tx] = v[(size_t)(r0 + ty + i * 8) * DDIM + c0 + tx];
    __syncthreads();
    int b = r0 >> 10;
    int kk0 = r0 & 1023;
#pragma unroll
    for (int i = 0; i < 4; i++) {
        float val = tile[tx][ty + i * 8];
        size_t o = ((size_t)(b << 10) + c0 + ty + i * 8) * 1024 + kk0 + tx;
        th[o] = __float2bfloat16_rn(val);
    }
}

// ---------------- fused masked softmax + head mean (2 heads / iter) ----------------
__global__ void __launch_bounds__(256) softmax_mean_kernel(
    const float* __restrict__ S, const void* __restrict__ mask,
    __nv_bfloat16* __restrict__ ah, float* __restrict__ mout)
{
    const int bq = blockIdx.x;
    const int b = bq >> 10, q = bq & 1023;
    const int t = threadIdx.x;
    const int k0 = t * 4;
    const int flag = g_mask_flag;
    const int lane = t & 31, w = t >> 5;

    bool mk[4];
#pragma unroll
    for (int i = 0; i < 4; i++) mk[i] = mask_valid(mask, b * KKL + k0 + i, flag);

    float macc[4] = {0.f, 0.f, 0.f, 0.f};
    __shared__ float red[16];
    const float NEG = -__int_as_float(0x7f800000);

    for (int h = 0; h < NH; h += 2) {
        const float* ra = S + (((size_t)(b * NH + h)) * QQL + q) * KKL;
        const float* rb = ra + (size_t)QQL * KKL;
        float4 a4 = *(const float4*)(ra + k0);
        float4 b4 = *(const float4*)(rb + k0);
        float va[4] = {a4.x, a4.y, a4.z, a4.w};
        float vb[4] = {b4.x, b4.y, b4.z, b4.w};
#pragma unroll
        for (int i = 0; i < 4; i++) if (!mk[i]) { va[i] = NEG; vb[i] = NEG; }

        float mxa = fmaxf(fmaxf(va[0], va[1]), fmaxf(va[2], va[3]));
        float mxb = fmaxf(fmaxf(vb[0], vb[1]), fmaxf(vb[2], vb[3]));
#pragma unroll
        for (int o = 16; o; o >>= 1) {
            mxa = fmaxf(mxa, __shfl_xor_sync(0xffffffffu, mxa, o));
            mxb = fmaxf(mxb, __shfl_xor_sync(0xffffffffu, mxb, o));
        }
        if (lane == 0) { red[w] = mxa; red[8 + w] = mxb; }
        __syncthreads();
        mxa = red[0]; mxb = red[8];
#pragma unroll
        for (int jj = 1; jj < 8; jj++) { mxa = fmaxf(mxa, red[jj]); mxb = fmaxf(mxb, red[8 + jj]); }
        __syncthreads();

        float sa = 0.f, sb = 0.f;
#pragma unroll
        for (int i = 0; i < 4; i++) {
            va[i] = expf(va[i] - mxa); sa += va[i];
            vb[i] = expf(vb[i] - mxb); sb += vb[i];
        }
#pragma unroll
        for (int o = 16; o; o >>= 1) {
            sa += __shfl_xor_sync(0xffffffffu, sa, o);
            sb += __shfl_xor_sync(0xffffffffu, sb, o);
        }
        if (lane == 0) { red[w] = sa; red[8 + w] = sb; }
        __syncthreads();
        float ta = red[0], tb = red[8];
#pragma unroll
        for (int jj = 1; jj < 8; jj++) { ta += red[jj]; tb += red[8 + jj]; }
        __syncthreads();
        float ia = 1.0f / ta, ib = 1.0f / tb;

        float pa0 = va[0] * ia, pa1 = va[1] * ia, pa2 = va[2] * ia, pa3 = va[3] * ia;
        float pb0 = vb[0] * ib, pb1 = vb[1] * ib, pb2 = vb[2] * ib, pb3 = vb[3] * ib;
        macc[0] += pa0 + pb0; macc[1] += pa1 + pb1;
        macc[2] += pa2 + pb2; macc[3] += pa3 + pb3;
        __nv_bfloat162* da = (__nv_bfloat162*)(ah + (((size_t)(b * NH + h)) * QQL + q) * KKL + k0);
        da[0] = __nv_bfloat162(__float2bfloat16_rn(pa0), __float2bfloat16_rn(pa1));
        da[1] = __nv_bfloat162(__float2bfloat16_rn(pa2), __float2bfloat16_rn(pa3));
        __nv_bfloat162* db = (__nv_bfloat162*)(ah + (((size_t)(b * NH + h + 1)) * QQL + q) * KKL + k0);
        db[0] = __nv_bfloat162(__float2bfloat16_rn(pb0), __float2bfloat16_rn(pb1));
        db[1] = __nv_bfloat162(__float2bfloat16_rn(pb2), __float2bfloat16_rn(pb3));
    }

    float4 mo;
    mo.x = macc[0] * (1.0f / NH); mo.y = macc[1] * (1.0f / NH);
    mo.z = macc[2] * (1.0f / NH); mo.w = macc[3] * (1.0f / NH);
    *(float4*)(mout + ((size_t)bq) * KKL + k0) = mo;
}

// ---------------- AV (mma.sync, 1-pass bf16, cp.async 2-stage) ----------------
#define AVP (128*GS)
#define BVP (64*GS)
__global__ void __launch_bounds__(256, 2) av_kernel(
    const __nv_bfloat16* __restrict__ attn, const __nv_bfloat16* __restrict__ vt,
    __nv_bfloat16* __restrict__ Ch)
{
    __shared__ __nv_bfloat16 sm[2 * (AVP + BVP)];
    const int tid = threadIdx.x;
    const int lane = tid & 31;
    const int warp = tid >> 5;
    const int wm = warp >> 2, wn = warp & 3;
    const int z = blockIdx.z;
    const int b = z / NH, h = z % NH;
    const size_t bm = (size_t)blockIdx.y * 128;

    const __nv_bfloat16* A = attn + (size_t)z * QQL * KKL;
    const __nv_bfloat16* W = vt + ((size_t)b * 1024 + h * 64) * 1024;
    const size_t Coff = (size_t)b * QQL * DDIM + h * HDIM;

    const int lrow = tid >> 1;
    const int lseg = (tid & 1) * 16;
    const __nv_bfloat16* gA = A + (bm + lrow) * (size_t)KKL + lseg;
    const int soffA = lrow * GS + lseg;
    const int brow = tid >> 2;
    const int bseg = (tid & 3) * 8;
    const __nv_bfloat16* gB = W + (size_t)brow * 1024 + bseg;
    const int soffB = brow * GS + bseg;

    const uint32_t smBase = smem_u32(sm);
    const int arow = wm * 64 + (lane & 15);
    const int acol = (lane >> 4) << 3;
    const int bg = lane >> 2;
    const int bt = (lane & 3) << 1;
    const int SP2 = AVP + BVP;

    float acc[4][2][4];
#pragma unroll
    for (int i = 0; i < 4; i++)
#pragma unroll
        for (int jq = 0; jq < 2; jq++)
#pragma unroll
            for (int t = 0; t < 4; t++) acc[i][jq][t] = 0.f;

    auto load_stage = [&](int st, int k0) {
        uint32_t d = smBase + (uint32_t)(st * SP2 + soffA) * 2;
        cpa16(d,      gA + k0);
        cpa16(d + 16, gA + k0 + 8);
        uint32_t db = smBase + (uint32_t)(st * SP2 + AVP + soffB) * 2;
        cpa16(db, gB + k0);
    };

    load_stage(0, 0);
    cpa_commit();

    for (int it = 0; it < 32; it++) {
        if (it + 1 < 32) { load_stage((it + 1) & 1, (it + 1) << 5); cpa_commit(); cpa_wait1(); }
        else cpa_wait0();
        __syncthreads();

        const int st = it & 1;
        const uint32_t aBase = smBase + (uint32_t)(st * SP2) * 2;
        const __nv_bfloat16* sB = sm + st * SP2 + AVP;

#pragma unroll
        for (int ks = 0; ks < 32; ks += 16) {
            uint32_t af[4][4];
#pragma unroll
            for (int mi = 0; mi < 4; mi++) {
                uint32_t off = (uint32_t)(((arow + mi * 16) * GS + ks + acol) * 2);
                ldsm_x4(af[mi], aBase + off);
            }
#pragma unroll
            for (int ni = 0; ni < 2; ni++) {
                int bidx = (wn * 16 + ni * 8 + bg) * GS + ks + bt;
                uint32_t b0 = *(const uint32_t*)&sB[bidx];
                uint32_t b1 = *(const uint32_t*)&sB[bidx + 8];
#pragma unroll
                for (int mi = 0; mi < 4; mi++)
                    mma_bf16(acc[mi][ni], af[mi], b0, b1);
            }
        }
        __syncthreads();
    }

    const int gr = lane >> 2;
    const int gc = (lane & 3) << 1;
#pragma unroll
    for (int mi = 0; mi < 4; mi++) {
        size_t r0 = bm + wm * 64 + mi * 16 + gr;
#pragma unroll
        for (int ni = 0; ni < 2; ni++) {
            int c0 = wn * 16 + ni * 8 + gc;
#pragma unroll
            for (int half = 0; half < 2; half++) {
                size_t row = r0 + half * 8;
                size_t o = Coff + row * DDIM + c0;
                *(__nv_bfloat162*)(Ch + o) = __nv_bfloat162(
                    __float2bfloat16_rn(acc[mi][ni][half * 2 + 0]),
                    __float2bfloat16_rn(acc[mi][ni][half * 2 + 1]));
            }
        }
    }
}

// ---------------- launch ----------------
extern "C" void kernel_launch(void* const* d_in, const int* in_sizes, int n_in,
                              void* d_out, int out_size)
{
    const float* query      = (const float*)d_in[0];
    const float* key_value  = (const float*)d_in[1];
    const void*  kpm        = d_in[2];
    const float* ln_q_w     = (const float*)d_in[3];
    const float* ln_q_b     = (const float*)d_in[4];
    const float* ln_kv_w    = (const float*)d_in[5];
    const float* ln_kv_b    = (const float*)d_in[6];
    const float* ln_f_w     = (const float*)d_in[7];
    const float* ln_f_b     = (const float*)d_in[8];
    const float* in_proj_w  = (const float*)d_in[9];
    const float* in_proj_b  = (const float*)d_in[10];
    const float* out_proj_w = (const float*)d_in[11];
    const float* out_proj_b = (const float*)d_in[12];
    const float* ffn_w1     = (const float*)d_in[13];
    const float* ffn_b1     = (const float*)d_in[14];
    const float* ffn_w2     = (const float*)d_in[15];
    const float* ffn_b2     = (const float*)d_in[16];

    float* out_x    = (float*)d_out;
    float* out_attn = out_x + (size_t)BB * QQL * DDIM;

    __nv_bfloat16 *qnh, *qnl, *kvnh, *kvnl, *lnfh, *lnfl, *aoh, *hh, *hl, *wh, *wl;
    __nv_bfloat16 *qph, *qpl, *kph, *kpl, *vth, *ath;
    float *vp, *sc, *xb;
    cudaGetSymbolAddress((void**)&qnh,  g_qn_h);  cudaGetSymbolAddress((void**)&qnl,  g_qn_l);
    cudaGetSymbolAddress((void**)&kvnh, g_kvn_h); cudaGetSymbolAddress((void**)&kvnl, g_kvn_l);
    cudaGetSymbolAddress((void**)&lnfh, g_lnf_h); cudaGetSymbolAddress((void**)&lnfl, g_lnf_l);
    cudaGetSymbolAddress((void**)&aoh,  g_ao_h);
    cudaGetSymbolAddress((void**)&hh,   g_hh);    cudaGetSymbolAddress((void**)&hl,   g_hl);
    cudaGetSymbolAddress((void**)&wh,   g_w_h);   cudaGetSymbolAddress((void**)&wl,   g_w_l);
    cudaGetSymbolAddress((void**)&qph,  g_qp_h);  cudaGetSymbolAddress((void**)&qpl,  g_qp_l);
    cudaGetSymbolAddress((void**)&kph,  g_kp_h);  cudaGetSymbolAddress((void**)&kpl,  g_kp_l);
    cudaGetSymbolAddress((void**)&vth,  g_vt_h);
    cudaGetSymbolAddress((void**)&ath,  g_attn_h);
    cudaGetSymbolAddress((void**)&vp,   g_v);
    cudaGetSymbolAddress((void**)&sc,   g_scores);
    cudaGetSymbolAddress((void**)&xb,   g_x);

    const size_t M1 = (size_t)1024 * 1024;
    const size_t OFF_OUT  = 3 * M1;
    const size_t OFF_FFN1 = 4 * M1;
    const size_t OFF_FFN2 = 8 * M1;

    const int SM3 = 2 * (2 * APLANE + 2 * BPLANE) * 2;   // 122880 B
    const int SM1 = 2 * (APLANE + BPLANE) * 2;           //  61440 B
    cudaFuncSetAttribute(gemm3_kernel, cudaFuncAttributeMaxDynamicSharedMemorySize, SM3);

    detect_mask_kernel<<<1, 256>>>((const unsigned char*)kpm);

    split_kernel<<<(unsigned)(3 * M1 / 1024), 256>>>(in_proj_w,  wh,            wl,            3 * M1);
    split_kernel<<<(unsigned)(1 * M1 / 1024), 256>>>(out_proj_w, wh + OFF_OUT,  wl + OFF_OUT,  1 * M1);
    split_kernel<<<(unsigned)(4 * M1 / 1024), 256>>>(ffn_w1,     wh + OFF_FFN1, wl + OFF_FFN1, 4 * M1);
    split_kernel<<<(unsigned)(4 * M1 / 1024), 256>>>(ffn_w2,     wh + OFF_FFN2, wl + OFF_FFN2, 4 * M1);

    ln_split_kernel<<<MROWS, 256>>>(query,     ln_q_w,  ln_q_b,  qnh,  qnl);
    ln_split_kernel<<<MROWS, 256>>>(key_value, ln_kv_w, ln_kv_b, kvnh, kvnl);

    dim3 g1024(DDIM / 128, MROWS / 256, 1);
    // q proj (3-pass -> bf16 hi/lo)
    gemm3_kernel<<<g1024, 512, SM3>>>(qnh, qnl, DDIM, 0, 0, wh, wl, DDIM, 0, 0,
                                 in_proj_b, nullptr, nullptr, qph, qpl, DDIM, 0, 0,
                                 DDIM, 1.f, 0, 1);
    // k proj (3-pass -> bf16 hi/lo)
    gemm3_kernel<<<g1024, 512, SM3>>>(kvnh, kvnl, DDIM, 0, 0, wh + M1, wl + M1, DDIM, 0, 0,
                                 in_proj_b + DDIM, nullptr, nullptr, kph, kpl, DDIM, 0, 0,
                                 DDIM, 1.f, 0, 1);
    // v proj (1-pass -> fp32)
    gemm3_kernel<<<g1024, 512, SM1>>>(kvnh, kvnh, DDIM, 0, 0, wh + 2 * M1, wh + 2 * M1, DDIM, 0, 0,
                                 in_proj_b + 2 * DDIM, nullptr, vp, nullptr, nullptr, DDIM, 0, 0,
                                 DDIM, 1.f, 0, 0);
    transpose_split_kernel<<<dim3(DDIM / 32, MROWS / 32), dim3(32, 8)>>>(vp, vth);

    // scores (3-pass batched, Kd=64, scale fused)
    dim3 gsc(KKL / 128, QQL / 256, BB * NH);
    gemm3_kernel<<<gsc, 512, SM3>>>(qph, qpl, DDIM, (long)QQL * DDIM, HDIM,
                               kph, kpl, DDIM, (long)KKL * DDIM, HDIM,
                               nullptr, nullptr, sc, nullptr, nullptr,
                               KKL, (long)NH * QQL * KKL, (long)QQL * KKL,
                               HDIM, 0.125f, 0, 1);

    softmax_mean_kernel<<<BB * QQL, 256>>>(sc, kpm, ath, out_attn);

    dim3 gav(1, QQL / 128, BB * NH);
    av_kernel<<<gav, 256>>>(ath, vth, aoh);

    // out_proj + residual (1-pass -> fp32)
    gemm3_kernel<<<g1024, 512, SM1>>>(aoh, aoh, DDIM, 0, 0, wh + OFF_OUT, wh + OFF_OUT, DDIM, 0, 0,
                                 out_proj_b, query, xb, nullptr, nullptr, DDIM, 0, 0,
                                 DDIM, 1.f, 0, 0);

    ln_split_kernel<<<MROWS, 256>>>(xb, ln_f_w, ln_f_b, lnfh, lnfl);

    // ffn1 (3-pass, gelu -> bf16 hi/lo)
    dim3 gff1(FFD / 128, MROWS / 256, 1);
    gemm3_kernel<<<gff1, 512, SM3>>>(lnfh, lnfl, DDIM, 0, 0, wh + OFF_FFN1, wl + OFF_FFN1, DDIM, 0, 0,
                                ffn_b1, nullptr, nullptr, hh, hl, FFD, 0, 0,
                                DDIM, 1.f, 1, 1);
    // ffn2 (3-pass, residual -> fp32)
    gemm3_kernel<<<g1024, 512, SM3>>>(hh, hl, FFD, 0, 0, wh + OFF_FFN2, wl + OFF_FFN2, FFD, 0, 0,
                                 ffn_b2, xb, out_x, nullptr, nullptr, DDIM, 0, 0,
                                 FFD, 1.f, 0, 1);
}

// round 10
// speedup vs baseline: 3.0537x; 1.0185x over previous
#include <cuda_runtime.h>
#include <cuda_bf16.h>
#include <math.h>
#include <stdint.h>

#define BB 8
#define QQL 1024
#define KKL 1024
#define DDIM 1024
#define NH 16
#define HDIM 64
#define FFD 4096
#define MROWS (BB*QQL)   /* 8192 */
#define GS 40            /* gemm3/av smem row stride (bf16 elems) */
#define APLANE (256*GS)
#define BPLANE (128*GS)

// ---------------- scratch (device globals) ----------------
__device__ __nv_bfloat16 g_xn_h[(size_t)2 * MROWS * DDIM],  g_xn_l[(size_t)2 * MROWS * DDIM];
__device__ __nv_bfloat16 g_qkp_h[(size_t)2 * MROWS * DDIM], g_qkp_l[(size_t)2 * MROWS * DDIM];
__device__ __nv_bfloat16 g_lnf_h[(size_t)MROWS * DDIM], g_lnf_l[(size_t)MROWS * DDIM];
__device__ __nv_bfloat16 g_vt_h[(size_t)MROWS * DDIM];
__device__ __nv_bfloat16 g_ao_h[(size_t)MROWS * DDIM];
__device__ __nv_bfloat16 g_hh[(size_t)MROWS * FFD],     g_hl[(size_t)MROWS * FFD];
__device__ __nv_bfloat16 g_w_h[(size_t)12 * 1024 * 1024], g_w_l[(size_t)12 * 1024 * 1024];
__device__ __nv_bfloat16 g_attn_h[(size_t)BB * NH * QQL * KKL];   // 256 MB
__device__ float g_v[(size_t)MROWS * DDIM];
__device__ float g_scores[(size_t)BB * NH * QQL * KKL];           // 512 MB
__device__ float g_x[(size_t)MROWS * DDIM];
__device__ int   g_mask_flag;

// ---------------- helpers ----------------
__device__ __forceinline__ uint32_t smem_u32(const void* p) {
    return (uint32_t)__cvta_generic_to_shared(p);
}
__device__ __forceinline__ void cpa16(uint32_t dst, const void* src) {
    asm volatile("cp.async.cg.shared.global [%0], [%1], 16;\n" :: "r"(dst), "l"(src));
}
__device__ __forceinline__ void cpa_commit() { asm volatile("cp.async.commit_group;\n"); }
__device__ __forceinline__ void cpa_wait0() { asm volatile("cp.async.wait_group 0;\n"); }
__device__ __forceinline__ void cpa_wait1() { asm volatile("cp.async.wait_group 1;\n"); }

__device__ __forceinline__ void mma_bf16(float* c, const uint32_t* a, uint32_t b0, uint32_t b1) {
    asm volatile(
        "mma.sync.aligned.m16n8k16.row.col.f32.bf16.bf16.f32 "
        "{%0,%1,%2,%3}, {%4,%5,%6,%7}, {%8,%9}, {%0,%1,%2,%3};\n"
        : "+f"(c[0]), "+f"(c[1]), "+f"(c[2]), "+f"(c[3])
        : "r"(a[0]), "r"(a[1]), "r"(a[2]), "r"(a[3]), "r"(b0), "r"(b1));
}
__device__ __forceinline__ void ldsm_x4(uint32_t* r, uint32_t addr) {
    asm volatile("ldmatrix.sync.aligned.m8n8.x4.shared.b16 {%0,%1,%2,%3}, [%4];\n"
                 : "=r"(r[0]), "=r"(r[1]), "=r"(r[2]), "=r"(r[3]) : "r"(addr));
}
__device__ __forceinline__ float gelu_exact(float v) {
    return 0.5f * v * (1.0f + erff(v * 0.70710678118654752f));
}

// ---------------- mask dtype sniffing ----------------
__global__ void detect_mask_kernel(const unsigned char* __restrict__ m) {
    __shared__ int c1, c2, c3;
    if (threadIdx.x == 0) { c1 = 0; c2 = 0; c3 = 0; }
    __syncthreads();
    for (int i = threadIdx.x; i < BB * KKL; i += blockDim.x) {
        unsigned char v = m[i];
        if (v) {
            int p = i & 3;
            if (p == 1) atomicAdd(&c1, 1);
            else if (p == 2) atomicAdd(&c2, 1);
            else if (p == 3) atomicAdd(&c3, 1);
        }
    }
    __syncthreads();
    if (threadIdx.x == 0) {
        int f;
        if (c1 == 0 && c2 == 0 && c3 == 0) f = 0;  // int32
        else if (c1 == 0) f = 2;                   // float32
        else f = 1;                                // uint8
        g_mask_flag = f;
    }
}

__device__ __forceinline__ bool mask_valid(const void* m, int idx, int flag) {
    if (flag == 1) return ((const unsigned char*)m)[idx] != 0;
    if (flag == 2) return ((const float*)m)[idx] != 0.0f;
    return ((const int*)m)[idx] != 0;
}

// ---------------- split fp32 -> bf16 hi/lo ----------------
__global__ void __launch_bounds__(256) split_kernel(
    const float* __restrict__ x, __nv_bfloat16* __restrict__ hi,
    __nv_bfloat16* __restrict__ lo, size_t n)
{
    size_t i = ((size_t)blockIdx.x * 256 + threadIdx.x) * 4;
    if (i >= n) return;
    float4 v = *(const float4*)(x + i);
    __nv_bfloat16 h0 = __float2bfloat16_rn(v.x);
    __nv_bfloat16 h1 = __float2bfloat16_rn(v.y);
    __nv_bfloat16 h2 = __float2bfloat16_rn(v.z);
    __nv_bfloat16 h3 = __float2bfloat16_rn(v.w);
    __nv_bfloat162* hp = (__nv_bfloat162*)(hi + i);
    hp[0] = __nv_bfloat162(h0, h1);
    hp[1] = __nv_bfloat162(h2, h3);
    __nv_bfloat162* lp = (__nv_bfloat162*)(lo + i);
    lp[0] = __nv_bfloat162(__float2bfloat16_rn(v.x - __bfloat162float(h0)),
                           __float2bfloat16_rn(v.y - __bfloat162float(h1)));
    lp[1] = __nv_bfloat162(__float2bfloat16_rn(v.z - __bfloat162float(h2)),
                           __float2bfloat16_rn(v.w - __bfloat162float(h3)));
}

// ---------------- layernorm -> split bf16 hi/lo ----------------
__global__ void __launch_bounds__(256) ln_split_kernel(
    const float* __restrict__ x, const float* __restrict__ w,
    const float* __restrict__ b, __nv_bfloat16* __restrict__ hi,
    __nv_bfloat16* __restrict__ lo)
{
    int row = blockIdx.x;
    const float* xr = x + (size_t)row * DDIM;
    float sum = 0.f, sumsq = 0.f;
    for (int i = threadIdx.x; i < DDIM; i += blockDim.x) {
        float v = xr[i]; sum += v; sumsq += v * v;
    }
    __shared__ float s1[32], s2[32];
    for (int o = 16; o; o >>= 1) {
        sum   += __shfl_down_sync(0xffffffffu, sum, o);
        sumsq += __shfl_down_sync(0xffffffffu, sumsq, o);
    }
    int lane = threadIdx.x & 31, wid = threadIdx.x >> 5;
    if (lane == 0) { s1[wid] = sum; s2[wid] = sumsq; }
    __syncthreads();
    if (wid == 0) {
        sum   = lane < 8 ? s1[lane] : 0.f;
        sumsq = lane < 8 ? s2[lane] : 0.f;
        for (int o = 4; o; o >>= 1) {
            sum   += __shfl_down_sync(0xffffffffu, sum, o);
            sumsq += __shfl_down_sync(0xffffffffu, sumsq, o);
        }
        if (lane == 0) { s1[0] = sum; s2[0] = sumsq; }
    }
    __syncthreads();
    float mu  = s1[0] * (1.0f / DDIM);
    float var = s2[0] * (1.0f / DDIM) - mu * mu;
    float inv = rsqrtf(var + 1e-5f);
    size_t base = (size_t)row * DDIM;
    for (int i = threadIdx.x; i < DDIM; i += blockDim.x) {
        float v = (xr[i] - mu) * inv * w[i] + b[i];
        __nv_bfloat16 h = __float2bfloat16_rn(v);
        hi[base + i] = h;
        lo[base + i] = __float2bfloat16_rn(v - __bfloat162float(h));
    }
}

// ---------------- split-bf16 GEMM, CTA tile 256x128, 512 threads ----------------
__global__ void __launch_bounds__(512, 1) gemm3_kernel(
    const __nv_bfloat16* __restrict__ Ah, const __nv_bfloat16* __restrict__ Al,
    long lda, long sAb, long sAhh,
    const __nv_bfloat16* __restrict__ Wh, const __nv_bfloat16* __restrict__ Wl,
    long ldb, long sBb, long sBhh,
    const float* __restrict__ bias, long sbias, const float* __restrict__ resid,
    float* __restrict__ Cf, __nv_bfloat16* __restrict__ Ch, __nv_bfloat16* __restrict__ Cl,
    long ldc, long sCb, long sChh,
    int Kd, float scale, int act, int three)
{
    extern __shared__ __nv_bfloat16 sm[];
    const int SP    = three ? (2 * APLANE + 2 * BPLANE) : (APLANE + BPLANE);
    const int offAl = APLANE;
    const int offBh = three ? 2 * APLANE : APLANE;
    const int offBl = 2 * APLANE + BPLANE;

    const int tid  = threadIdx.x;
    const int lane = tid & 31;
    const int warp = tid >> 5;
    const int wm = warp >> 2, wn = warp & 3;
    const int zb = blockIdx.z / NH, zh = blockIdx.z % NH;
    const size_t Aoff = (size_t)zb * sAb + (size_t)zh * sAhh;
    const size_t Boff = (size_t)zb * sBb + (size_t)zh * sBhh;
    const size_t Coff = (size_t)zb * sCb + (size_t)zh * sChh;
    const size_t bm = (size_t)blockIdx.y * 256, bn = (size_t)blockIdx.x * 128;
    const float* bptr = bias ? bias + (size_t)zh * sbias : nullptr;

    const int lr   = tid >> 2;
    const int lseg = (tid & 3) * 8;
    const __nv_bfloat16* gAh1 = Ah + Aoff + (bm + lr) * (size_t)lda + lseg;
    const __nv_bfloat16* gAh2 = gAh1 + 128 * (size_t)lda;
    const __nv_bfloat16* gAl1 = Al + Aoff + (bm + lr) * (size_t)lda + lseg;
    const __nv_bfloat16* gAl2 = gAl1 + 128 * (size_t)lda;
    const __nv_bfloat16* gBh  = Wh + Boff + (bn + lr) * (size_t)ldb + lseg;
    const __nv_bfloat16* gBl  = Wl + Boff + (bn + lr) * (size_t)ldb + lseg;
    const int soffA1 = lr * GS + lseg;
    const int soffA2 = soffA1 + 128 * GS;
    const int soffB  = lr * GS + lseg;

    const uint32_t smBase = smem_u32(sm);
    const int arow = wm * 64 + (lane & 15);
    const int acol = (lane >> 4) << 3;
    const int bg = lane >> 2;
    const int bt = (lane & 3) << 1;

    float acc[4][4][4];
#pragma unroll
    for (int i = 0; i < 4; i++)
#pragma unroll
        for (int j = 0; j < 4; j++)
#pragma unroll
            for (int t = 0; t < 4; t++) acc[i][j][t] = 0.f;

    const int ntiles = Kd >> 5;

    auto load_stage = [&](int st, int k0) {
        uint32_t base = smBase + (uint32_t)(st * SP) * 2;
        cpa16(base + (uint32_t)soffA1 * 2, gAh1 + k0);
        cpa16(base + (uint32_t)soffA2 * 2, gAh2 + k0);
        cpa16(base + (uint32_t)(offBh + soffB) * 2, gBh + k0);
        if (three) {
            cpa16(base + (uint32_t)(offAl + soffA1) * 2, gAl1 + k0);
            cpa16(base + (uint32_t)(offAl + soffA2) * 2, gAl2 + k0);
            cpa16(base + (uint32_t)(offBl + soffB) * 2, gBl + k0);
        }
    };

    load_stage(0, 0);
    cpa_commit();

    for (int it = 0; it < ntiles; it++) {
        if (it + 1 < ntiles) { load_stage((it + 1) & 1, (it + 1) << 5); cpa_commit(); cpa_wait1(); }
        else cpa_wait0();
        __syncthreads();

        const int st = it & 1;
        const uint32_t aH = smBase + (uint32_t)(st * SP) * 2;
        const uint32_t aL = aH + (uint32_t)offAl * 2;
        const __nv_bfloat16* sBh = sm + st * SP + offBh;
        const __nv_bfloat16* sBl = sm + st * SP + offBl;

#pragma unroll
        for (int ks = 0; ks < 32; ks += 16) {
            uint32_t afh[4][4], afl[4][4];
#pragma unroll
            for (int mi = 0; mi < 4; mi++) {
                uint32_t off = (uint32_t)(((arow + mi * 16) * GS + ks + acol) * 2);
                ldsm_x4(afh[mi], aH + off);
                if (three) ldsm_x4(afl[mi], aL + off);
            }
#pragma unroll
            for (int ni = 0; ni < 4; ni++) {
                int bidx = (wn * 32 + ni * 8 + bg) * GS + ks + bt;
                uint32_t bh0 = *(const uint32_t*)&sBh[bidx];
                uint32_t bh1 = *(const uint32_t*)&sBh[bidx + 8];
#pragma unroll
                for (int mi = 0; mi < 4; mi++)
                    mma_bf16(acc[mi][ni], afh[mi], bh0, bh1);
                if (three) {
                    uint32_t bl0 = *(const uint32_t*)&sBl[bidx];
                    uint32_t bl1 = *(const uint32_t*)&sBl[bidx + 8];
#pragma unroll
                    for (int mi = 0; mi < 4; mi++) {
                        mma_bf16(acc[mi][ni], afl[mi], bh0, bh1);
                        mma_bf16(acc[mi][ni], afh[mi], bl0, bl1);
                    }
                }
            }
        }
        __syncthreads();
    }

    const int gr = lane >> 2;
    const int gc = (lane & 3) << 1;
#pragma unroll
    for (int mi = 0; mi < 4; mi++) {
        size_t r0 = bm + wm * 64 + mi * 16 + gr;
#pragma unroll
        for (int ni = 0; ni < 4; ni++) {
            size_t c0 = bn + wn * 32 + ni * 8 + gc;
            float bv0 = bptr ? bptr[c0] : 0.f;
            float bv1 = bptr ? bptr[c0 + 1] : 0.f;
#pragma unroll
            for (int half = 0; half < 2; half++) {
                size_t row = r0 + half * 8;
                float v0 = acc[mi][ni][half * 2 + 0] * scale + bv0;
                float v1 = acc[mi][ni][half * 2 + 1] * scale + bv1;
                size_t o = Coff + row * ldc + c0;
                if (resid) {
                    float2 rv = *(const float2*)(resid + o);
                    v0 += rv.x; v1 += rv.y;
                }
                if (act) { v0 = gelu_exact(v0); v1 = gelu_exact(v1); }
                if (Cf) *(float2*)(Cf + o) = make_float2(v0, v1);
                if (Ch) {
                    __nv_bfloat16 h0 = __float2bfloat16_rn(v0);
                    __nv_bfloat16 h1 = __float2bfloat16_rn(v1);
                    *(__nv_bfloat162*)(Ch + o) = __nv_bfloat162(h0, h1);
                    *(__nv_bfloat162*)(Cl + o) = __nv_bfloat162(
                        __float2bfloat16_rn(v0 - __bfloat162float(h0)),
                        __float2bfloat16_rn(v1 - __bfloat162float(h1)));
                }
            }
        }
    }
}

// ---------------- dedicated scores kernel ----------------
// S[b,h,q,k] = 0.125 * <q_bh[q,:], k_bh[k,:]>, 3-pass split-bf16.
// CTA: 256 q-rows x all 1024 keys (8 tiles of 128). Q tile persistent in smem.
#define SGS 72                 /* smem row stride (64 data + 8 pad), 144B rows */
#define SAPL (256*SGS)         /* A plane elems */
#define SBPL (128*SGS)         /* B plane elems */
__global__ void __launch_bounds__(512, 1) scores_kernel(
    const __nv_bfloat16* __restrict__ qh, const __nv_bfloat16* __restrict__ ql,
    const __nv_bfloat16* __restrict__ kh, const __nv_bfloat16* __restrict__ kl,
    float* __restrict__ S)
{
    extern __shared__ __nv_bfloat16 sm[];
    const int offAl = SAPL;
    const int offB  = 2 * SAPL;
    const int BSTG  = 2 * SBPL;

    const int tid = threadIdx.x, lane = tid & 31, warp = tid >> 5;
    const int wm = warp >> 2, wn = warp & 3;
    const int z = blockIdx.z, b = z / NH, h = z % NH;
    const size_t bm = (size_t)blockIdx.y * 256;
    const __nv_bfloat16* Ah = qh + (size_t)b * QQL * DDIM + h * HDIM;
    const __nv_bfloat16* Al = ql + (size_t)b * QQL * DDIM + h * HDIM;
    const __nv_bfloat16* Bh = kh + (size_t)b * KKL * DDIM + h * HDIM;
    const __nv_bfloat16* Bl = kl + (size_t)b * KKL * DDIM + h * HDIM;
    float* C = S + ((size_t)(b * NH + h) * QQL + bm) * KKL;

    const uint32_t smBase = smem_u32(sm);

    // A: 256 rows x 64 cols (hi+lo), 4 chunks/thread/plane
#pragma unroll
    for (int i = 0; i < 4; i++) {
        int c = tid + 512 * i;
        int row = c >> 3;
        int seg = (c & 7) * 8;
        uint32_t d = smBase + (uint32_t)(row * SGS + seg) * 2;
        cpa16(d, Ah + (bm + row) * (size_t)DDIM + seg);
        cpa16(d + (uint32_t)offAl * 2, Al + (bm + row) * (size_t)DDIM + seg);
    }
    auto load_B = [&](int st, int kt) {
        uint32_t base = smBase + (uint32_t)(offB + st * BSTG) * 2;
#pragma unroll
        for (int i = 0; i < 2; i++) {
            int c = tid + 512 * i;
            int row = c >> 3;
            int seg = (c & 7) * 8;
            uint32_t d = base + (uint32_t)(row * SGS + seg) * 2;
            cpa16(d, Bh + (size_t)(kt * 128 + row) * DDIM + seg);
            cpa16(d + (uint32_t)SBPL * 2, Bl + (size_t)(kt * 128 + row) * DDIM + seg);
        }
    };
    load_B(0, 0);
    cpa_commit();

    const int arow = wm * 64 + (lane & 15);
    const int acol = (lane >> 4) << 3;
    const int bg = lane >> 2, bt = (lane & 3) << 1;
    const uint32_t aH = smBase;
    const uint32_t aL = smBase + (uint32_t)offAl * 2;
    const int gr = lane >> 2;
    const int gc = (lane & 3) << 1;

    for (int kt = 0; kt < 8; kt++) {
        if (kt + 1 < 8) { load_B((kt + 1) & 1, kt + 1); cpa_commit(); cpa_wait1(); }
        else cpa_wait0();
        __syncthreads();
        const __nv_bfloat16* sBh = sm + offB + (kt & 1) * BSTG;
        const __nv_bfloat16* sBl = sBh + SBPL;

        float acc[4][4][4];
#pragma unroll
        for (int i = 0; i < 4; i++)
#pragma unroll
            for (int j = 0; j < 4; j++)
#pragma unroll
                for (int t = 0; t < 4; t++) acc[i][j][t] = 0.f;

#pragma unroll
        for (int ks = 0; ks < 64; ks += 16) {
            uint32_t afh[4][4], afl[4][4];
#pragma unroll
            for (int mi = 0; mi < 4; mi++) {
                uint32_t off = (uint32_t)(((arow + mi * 16) * SGS + ks + acol) * 2);
                ldsm_x4(afh[mi], aH + off);
                ldsm_x4(afl[mi], aL + off);
            }
#pragma unroll
            for (int ni = 0; ni < 4; ni++) {
                int bidx = (wn * 32 + ni * 8 + bg) * SGS + ks + bt;
                uint32_t bh0 = *(const uint32_t*)&sBh[bidx];
                uint32_t bh1 = *(const uint32_t*)&sBh[bidx + 8];
                uint32_t bl0 = *(const uint32_t*)&sBl[bidx];
                uint32_t bl1 = *(const uint32_t*)&sBl[bidx + 8];
#pragma unroll
                for (int mi = 0; mi < 4; mi++) {
                    mma_bf16(acc[mi][ni], afh[mi], bh0, bh1);
                    mma_bf16(acc[mi][ni], afl[mi], bh0, bh1);
                    mma_bf16(acc[mi][ni], afh[mi], bl0, bl1);
                }
            }
        }

#pragma unroll
        for (int mi = 0; mi < 4; mi++) {
            size_t r0 = wm * 64 + mi * 16 + gr;
#pragma unroll
            for (int ni = 0; ni < 4; ni++) {
                size_t c0 = (size_t)kt * 128 + wn * 32 + ni * 8 + gc;
#pragma unroll
                for (int half = 0; half < 2; half++) {
                    size_t row = r0 + half * 8;
                    *(float2*)(C + row * KKL + c0) = make_float2(
                        acc[mi][ni][half * 2 + 0] * 0.125f,
                        acc[mi][ni][half * 2 + 1] * 0.125f);
                }
            }
        }
        __syncthreads();
    }
}

// ---------------- transpose V (fp32 -> bf16, [b,k,c] -> [b,c,k]) ----------------
__global__ void __launch_bounds__(256) transpose_split_kernel(
    const float* __restrict__ v, __nv_bfloat16* __restrict__ th)
{
    __shared__ float tile[32][33];
    int tx = threadIdx.x, ty = threadIdx.y;
    int c0 = blockIdx.x * 32;
    int r0 = blockIdx.y * 32;
#pragma unroll
    for (int i = 0; i < 4; i++)
        tile[ty + i * 8][tx] = v[(size_t)(r0 + ty + i * 8) * DDIM + c0 + tx];
    __syncthreads();
    int b = r0 >> 10;
    int kk0 = r0 & 1023;
#pragma unroll
    for (int i = 0; i < 4; i++) {
        float val = tile[tx][ty + i * 8];
        size_t o = ((size_t)(b << 10) + c0 + ty + i * 8) * 1024 + kk0 + tx;
        th[o] = __float2bfloat16_rn(val);
    }
}

// ---------------- fused masked softmax + head mean (2 heads / iter) ----------------
__global__ void __launch_bounds__(256) softmax_mean_kernel(
    const float* __restrict__ S, const void* __restrict__ mask,
    __nv_bfloat16* __restrict__ ah, float* __restrict__ mout)
{
    const int bq = blockIdx.x;
    const int b = bq >> 10, q = bq & 1023;
    const int t = threadIdx.x;
    const int k0 = t * 4;
    const int flag = g_mask_flag;
    const int lane = t & 31, w = t >> 5;

    bool mk[4];
#pragma unroll
    for (int i = 0; i < 4; i++) mk[i] = mask_valid(mask, b * KKL + k0 + i, flag);

    float macc[4] = {0.f, 0.f, 0.f, 0.f};
    __shared__ float red[16];
    const float NEG = -__int_as_float(0x7f800000);

    for (int h = 0; h < NH; h += 2) {
        const float* ra = S + (((size_t)(b * NH + h)) * QQL + q) * KKL;
        const float* rb = ra + (size_t)QQL * KKL;
        float4 a4 = *(const float4*)(ra + k0);
        float4 b4 = *(const float4*)(rb + k0);
        float va[4] = {a4.x, a4.y, a4.z, a4.w};
        float vb[4] = {b4.x, b4.y, b4.z, b4.w};
#pragma unroll
        for (int i = 0; i < 4; i++) if (!mk[i]) { va[i] = NEG; vb[i] = NEG; }

        float mxa = fmaxf(fmaxf(va[0], va[1]), fmaxf(va[2], va[3]));
        float mxb = fmaxf(fmaxf(vb[0], vb[1]), fmaxf(vb[2], vb[3]));
#pragma unroll
        for (int o = 16; o; o >>= 1) {
            mxa = fmaxf(mxa, __shfl_xor_sync(0xffffffffu, mxa, o));
            mxb = fmaxf(mxb, __shfl_xor_sync(0xffffffffu, mxb, o));
        }
        if (lane == 0) { red[w] = mxa; red[8 + w] = mxb; }
        __syncthreads();
        mxa = red[0]; mxb = red[8];
#pragma unroll
        for (int jj = 1; jj < 8; jj++) { mxa = fmaxf(mxa, red[jj]); mxb = fmaxf(mxb, red[8 + jj]); }
        __syncthreads();

        float sa = 0.f, sb = 0.f;
#pragma unroll
        for (int i = 0; i < 4; i++) {
            va[i] = expf(va[i] - mxa); sa += va[i];
            vb[i] = expf(vb[i] - mxb); sb += vb[i];
        }
#pragma unroll
        for (int o = 16; o; o >>= 1) {
            sa += __shfl_xor_sync(0xffffffffu, sa, o);
            sb += __shfl_xor_sync(0xffffffffu, sb, o);
        }
        if (lane == 0) { red[w] = sa; red[8 + w] = sb; }
        __syncthreads();
        float ta = red[0], tb = red[8];
#pragma unroll
        for (int jj = 1; jj < 8; jj++) { ta += red[jj]; tb += red[8 + jj]; }
        __syncthreads();
        float ia = 1.0f / ta, ib = 1.0f / tb;

        float pa0 = va[0] * ia, pa1 = va[1] * ia, pa2 = va[2] * ia, pa3 = va[3] * ia;
        float pb0 = vb[0] * ib, pb1 = vb[1] * ib, pb2 = vb[2] * ib, pb3 = vb[3] * ib;
        macc[0] += pa0 + pb0; macc[1] += pa1 + pb1;
        macc[2] += pa2 + pb2; macc[3] += pa3 + pb3;
        __nv_bfloat162* da = (__nv_bfloat162*)(ah + (((size_t)(b * NH + h)) * QQL + q) * KKL + k0);
        da[0] = __nv_bfloat162(__float2bfloat16_rn(pa0), __float2bfloat16_rn(pa1));
        da[1] = __nv_bfloat162(__float2bfloat16_rn(pa2), __float2bfloat16_rn(pa3));
        __nv_bfloat162* db = (__nv_bfloat162*)(ah + (((size_t)(b * NH + h + 1)) * QQL + q) * KKL + k0);
        db[0] = __nv_bfloat162(__float2bfloat16_rn(pb0), __float2bfloat16_rn(pb1));
        db[1] = __nv_bfloat162(__float2bfloat16_rn(pb2), __float2bfloat16_rn(pb3));
    }

    float4 mo;
    mo.x = macc[0] * (1.0f / NH); mo.y = macc[1] * (1.0f / NH);
    mo.z = macc[2] * (1.0f / NH); mo.w = macc[3] * (1.0f / NH);
    *(float4*)(mout + ((size_t)bq) * KKL + k0) = mo;
}

// ---------------- AV (mma.sync, 1-pass bf16, cp.async 2-stage) ----------------
#define AVP (128*GS)
#define BVP (64*GS)
__global__ void __launch_bounds__(256, 2) av_kernel(
    const __nv_bfloat16* __restrict__ attn, const __nv_bfloat16* __restrict__ vt,
    __nv_bfloat16* __restrict__ Ch)
{
    __shared__ __nv_bfloat16 sm[2 * (AVP + BVP)];
    const int tid = threadIdx.x;
    const int lane = tid & 31;
    const int warp = tid >> 5;
    const int wm = warp >> 2, wn = warp & 3;
    const int z = blockIdx.z;
    const int b = z / NH, h = z % NH;
    const size_t bm = (size_t)blockIdx.y * 128;

    const __nv_bfloat16* A = attn + (size_t)z * QQL * KKL;
    const __nv_bfloat16* W = vt + ((size_t)b * 1024 + h * 64) * 1024;
    const size_t Coff = (size_t)b * QQL * DDIM + h * HDIM;

    const int lrow = tid >> 1;
    const int lseg = (tid & 1) * 16;
    const __nv_bfloat16* gA = A + (bm + lrow) * (size_t)KKL + lseg;
    const int soffA = lrow * GS + lseg;
    const int brow = tid >> 2;
    const int bseg = (tid & 3) * 8;
    const __nv_bfloat16* gB = W + (size_t)brow * 1024 + bseg;
    const int soffB = brow * GS + bseg;

    const uint32_t smBase = smem_u32(sm);
    const int arow = wm * 64 + (lane & 15);
    const int acol = (lane >> 4) << 3;
    const int bg = lane >> 2;
    const int bt = (lane & 3) << 1;
    const int SP2 = AVP + BVP;

    float acc[4][2][4];
#pragma unroll
    for (int i = 0; i < 4; i++)
#pragma unroll
        for (int jq = 0; jq < 2; jq++)
#pragma unroll
            for (int t = 0; t < 4; t++) acc[i][jq][t] = 0.f;

    auto load_stage = [&](int st, int k0) {
        uint32_t d = smBase + (uint32_t)(st * SP2 + soffA) * 2;
        cpa16(d,      gA + k0);
        cpa16(d + 16, gA + k0 + 8);
        uint32_t db = smBase + (uint32_t)(st * SP2 + AVP + soffB) * 2;
        cpa16(db, gB + k0);
    };

    load_stage(0, 0);
    cpa_commit();

    for (int it = 0; it < 32; it++) {
        if (it + 1 < 32) { load_stage((it + 1) & 1, (it + 1) << 5); cpa_commit(); cpa_wait1(); }
        else cpa_wait0();
        __syncthreads();

        const int st = it & 1;
        const uint32_t aBase = smBase + (uint32_t)(st * SP2) * 2;
        const __nv_bfloat16* sB = sm + st * SP2 + AVP;

#pragma unroll
        for (int ks = 0; ks < 32; ks += 16) {
            uint32_t af[4][4];
#pragma unroll
            for (int mi = 0; mi < 4; mi++) {
                uint32_t off = (uint32_t)(((arow + mi * 16) * GS + ks + acol) * 2);
                ldsm_x4(af[mi], aBase + off);
            }
#pragma unroll
            for (int ni = 0; ni < 2; ni++) {
                int bidx = (wn * 16 + ni * 8 + bg) * GS + ks + bt;
                uint32_t b0 = *(const uint32_t*)&sB[bidx];
                uint32_t b1 = *(const uint32_t*)&sB[bidx + 8];
#pragma unroll
                for (int mi = 0; mi < 4; mi++)
                    mma_bf16(acc[mi][ni], af[mi], b0, b1);
            }
        }
        __syncthreads();
    }

    const int gr = lane >> 2;
    const int gc = (lane & 3) << 1;
#pragma unroll
    for (int mi = 0; mi < 4; mi++) {
        size_t r0 = bm + wm * 64 + mi * 16 + gr;
#pragma unroll
        for (int ni = 0; ni < 2; ni++) {
            int c0 = wn * 16 + ni * 8 + gc;
#pragma unroll
            for (int half = 0; half < 2; half++) {
                size_t row = r0 + half * 8;
                size_t o = Coff + row * DDIM + c0;
                *(__nv_bfloat162*)(Ch + o) = __nv_bfloat162(
                    __float2bfloat16_rn(acc[mi][ni][half * 2 + 0]),
                    __float2bfloat16_rn(acc[mi][ni][half * 2 + 1]));
            }
        }
    }
}

// ---------------- launch ----------------
extern "C" void kernel_launch(void* const* d_in, const int* in_sizes, int n_in,
                              void* d_out, int out_size)
{
    const float* query      = (const float*)d_in[0];
    const float* key_value  = (const float*)d_in[1];
    const void*  kpm        = d_in[2];
    const float* ln_q_w     = (const float*)d_in[3];
    const float* ln_q_b     = (const float*)d_in[4];
    const float* ln_kv_w    = (const float*)d_in[5];
    const float* ln_kv_b    = (const float*)d_in[6];
    const float* ln_f_w     = (const float*)d_in[7];
    const float* ln_f_b     = (const float*)d_in[8];
    const float* in_proj_w  = (const float*)d_in[9];
    const float* in_proj_b  = (const float*)d_in[10];
    const float* out_proj_w = (const float*)d_in[11];
    const float* out_proj_b = (const float*)d_in[12];
    const float* ffn_w1     = (const float*)d_in[13];
    const float* ffn_b1     = (const float*)d_in[14];
    const float* ffn_w2     = (const float*)d_in[15];
    const float* ffn_b2     = (const float*)d_in[16];

    float* out_x    = (float*)d_out;
    float* out_attn = out_x + (size_t)BB * QQL * DDIM;

    __nv_bfloat16 *xnh, *xnl, *qkph, *qkpl, *lnfh, *lnfl, *aoh, *hh, *hl, *wh, *wl;
    __nv_bfloat16 *vth, *ath;
    float *vp, *sc, *xb;
    cudaGetSymbolAddress((void**)&xnh,  g_xn_h);  cudaGetSymbolAddress((void**)&xnl,  g_xn_l);
    cudaGetSymbolAddress((void**)&qkph, g_qkp_h); cudaGetSymbolAddress((void**)&qkpl, g_qkp_l);
    cudaGetSymbolAddress((void**)&lnfh, g_lnf_h); cudaGetSymbolAddress((void**)&lnfl, g_lnf_l);
    cudaGetSymbolAddress((void**)&aoh,  g_ao_h);
    cudaGetSymbolAddress((void**)&hh,   g_hh);    cudaGetSymbolAddress((void**)&hl,   g_hl);
    cudaGetSymbolAddress((void**)&wh,   g_w_h);   cudaGetSymbolAddress((void**)&wl,   g_w_l);
    cudaGetSymbolAddress((void**)&vth,  g_vt_h);
    cudaGetSymbolAddress((void**)&ath,  g_attn_h);
    cudaGetSymbolAddress((void**)&vp,   g_v);
    cudaGetSymbolAddress((void**)&sc,   g_scores);
    cudaGetSymbolAddress((void**)&xb,   g_x);

    const size_t M1 = (size_t)1024 * 1024;
    const size_t MD = (size_t)MROWS * DDIM;
    const size_t OFF_OUT  = 3 * M1;
    const size_t OFF_FFN1 = 4 * M1;
    const size_t OFF_FFN2 = 8 * M1;

    const int SM3 = 2 * (2 * APLANE + 2 * BPLANE) * 2;   // 122880 B
    const int SM1 = 2 * (APLANE + BPLANE) * 2;           //  61440 B
    const int SMS = (2 * SAPL + 2 * 2 * SBPL) * 2;       // 147456 B
    cudaFuncSetAttribute(gemm3_kernel,  cudaFuncAttributeMaxDynamicSharedMemorySize, SM3);
    cudaFuncSetAttribute(scores_kernel, cudaFuncAttributeMaxDynamicSharedMemorySize, SMS);

    detect_mask_kernel<<<1, 256>>>((const unsigned char*)kpm);

    split_kernel<<<(unsigned)(3 * M1 / 1024), 256>>>(in_proj_w,  wh,            wl,            3 * M1);
    split_kernel<<<(unsigned)(1 * M1 / 1024), 256>>>(out_proj_w, wh + OFF_OUT,  wl + OFF_OUT,  1 * M1);
    split_kernel<<<(unsigned)(4 * M1 / 1024), 256>>>(ffn_w1,     wh + OFF_FFN1, wl + OFF_FFN1, 4 * M1);
    split_kernel<<<(unsigned)(4 * M1 / 1024), 256>>>(ffn_w2,     wh + OFF_FFN2, wl + OFF_FFN2, 4 * M1);

    ln_split_kernel<<<MROWS, 256>>>(query,     ln_q_w,  ln_q_b,  xnh,      xnl);
    ln_split_kernel<<<MROWS, 256>>>(key_value, ln_kv_w, ln_kv_b, xnh + MD, xnl + MD);

    // merged q+k proj (3-pass, z=2), outputs bf16 hi/lo into combined buffer
    dim3 gqk(DDIM / 128, MROWS / 256, 2);
    gemm3_kernel<<<gqk, 512, SM3>>>(xnh, xnl, DDIM, 0, (long)MD,
                                    wh, wl, DDIM, 0, (long)M1,
                                    in_proj_b, DDIM, nullptr,
                                    nullptr, qkph, qkpl, DDIM, 0, (long)MD,
                                    DDIM, 1.f, 0, 1);
    // v proj (1-pass -> fp32)
    dim3 g1024(DDIM / 128, MROWS / 256, 1);
    gemm3_kernel<<<g1024, 512, SM1>>>(xnh + MD, xnh + MD, DDIM, 0, 0,
                                      wh + 2 * M1, wh + 2 * M1, DDIM, 0, 0,
                                      in_proj_b + 2 * DDIM, 0, nullptr,
                                      vp, nullptr, nullptr, DDIM, 0, 0,
                                      DDIM, 1.f, 0, 0);
    transpose_split_kernel<<<dim3(DDIM / 32, MROWS / 32), dim3(32, 8)>>>(vp, vth);

    // scores: dedicated persistent-A kernel
    dim3 gsc(1, QQL / 256, BB * NH);
    scores_kernel<<<gsc, 512, SMS>>>(qkph, qkpl, qkph + MD, qkpl + MD, sc);

    softmax_mean_kernel<<<BB * QQL, 256>>>(sc, kpm, ath, out_attn);

    dim3 gav(1, QQL / 128, BB * NH);
    av_kernel<<<gav, 256>>>(ath, vth, aoh);

    // out_proj + residual (1-pass -> fp32)
    gemm3_kernel<<<g1024, 512, SM1>>>(aoh, aoh, DDIM, 0, 0,
                                      wh + OFF_OUT, wh + OFF_OUT, DDIM, 0, 0,
                                      out_proj_b, 0, query,
                                      xb, nullptr, nullptr, DDIM, 0, 0,
                                      DDIM, 1.f, 0, 0);

    ln_split_kernel<<<MROWS, 256>>>(xb, ln_f_w, ln_f_b, lnfh, lnfl);

    // ffn1 (3-pass, gelu -> bf16 hi/lo)
    dim3 gff1(FFD / 128, MROWS / 256, 1);
    gemm3_kernel<<<gff1, 512, SM3>>>(lnfh, lnfl, DDIM, 0, 0,
                                     wh + OFF_FFN1, wl + OFF_FFN1, DDIM, 0, 0,
                                     ffn_b1, 0, nullptr,
                                     nullptr, hh, hl, FFD, 0, 0,
                                     DDIM, 1.f, 1, 1);
    // ffn2 (3-pass, residual -> fp32)
    gemm3_kernel<<<g1024, 512, SM3>>>(hh, hl, FFD, 0, 0,
                                      wh + OFF_FFN2, wl + OFF_FFN2, FFD, 0, 0,
                                      ffn_b2, 0, xb,
                                      out_x, nullptr, nullptr, DDIM, 0, 0,
                                      FFD, 1.f, 0, 1);
}